// round 9
// baseline (speedup 1.0000x reference)
#include <cuda_runtime.h>
#include <cuda_fp16.h>
#include <math.h>
#include <stdint.h>

#define BATCH 2048
#define FEAT  2048
#define HARM  32
#define DIN   (FEAT + 2*HARM)   /* 2112 */
#define NEXP  8
#define EDIM  32
#define HID   1024
#define VOCAB 50257
#define NPAD  50432             /* 197 * 256 */
#define NT256 197
#define MT128 16

// ---------------- device scratch (no allocations allowed) ----------------
__device__ __align__(16) float  g_ctx[BATCH * HID];          // 8 MB
__device__ __align__(16) float  g_gain[HID];
__device__ __align__(16) __half g_A_hi[BATCH * HID];         // [2048][1024]
__device__ __align__(16) __half g_B_hi[(size_t)NPAD * HID];  // [NPAD][1024] (Wout^T)

__device__ __forceinline__ uint32_t smem_u32(const void* p) {
    uint32_t a;
    asm("{ .reg .u64 t; cvta.to.shared.u64 t, %1; cvt.u32.u64 %0, t; }" : "=r"(a) : "l"(p));
    return a;
}

#define LDSM_X4(r, a) asm volatile( \
    "ldmatrix.sync.aligned.m8n8.x4.shared.b16 {%0,%1,%2,%3}, [%4];" \
    : "=r"((r)[0]),"=r"((r)[1]),"=r"((r)[2]),"=r"((r)[3]) : "r"(a))
#define MMA16816(c, a, b) asm volatile( \
    "mma.sync.aligned.m16n8k16.row.col.f32.f16.f16.f32 " \
    "{%0,%1,%2,%3},{%4,%5,%6,%7},{%8,%9},{%0,%1,%2,%3};" \
    : "+f"((c)[0]),"+f"((c)[1]),"+f"((c)[2]),"+f"((c)[3]) \
    : "r"((a)[0]),"r"((a)[1]),"r"((a)[2]),"r"((a)[3]), "r"((b)[0]),"r"((b)[1]))
#define CP_ASYNC16(d, s) asm volatile( \
    "cp.async.cg.shared.global [%0], [%1], 16;" :: "r"(d), "l"(s) : "memory")
#define CP_COMMIT() asm volatile("cp.async.commit_group;" ::: "memory")
#define CP_WAIT1()  asm volatile("cp.async.wait_group 1;" ::: "memory")
#define CP_WAIT0()  asm volatile("cp.async.wait_group 0;" ::: "memory")

// ============================================================
// Kernel 1 (merged prep):
//   blocks [0,256)       : fused ctx pipeline, 8 samples per block
//   blocks [256, 256+6304): Wout f32 [K][N] -> fp16 [NPAD][K] transpose
// These are independent; merging lets them overlap in one launch.
// ============================================================
#define CTX_BLOCKS  256
#define WOUT_BLOCKS (16 * 394)          /* kchunks x 128-wide n tiles */
#define PREP_SMEM   (8*DIN*4 + 8*256*4 + 8*8*4 + 8*32*4)   /* 77056 B */

__global__ __launch_bounds__(256) void prep_kernel(
    const float* __restrict__ x,
    const float* __restrict__ Wg, const float* __restrict__ bg,
    const float* __restrict__ We, const float* __restrict__ be,
    const float* __restrict__ Wo, const float* __restrict__ bo,
    const float* __restrict__ W)
{
    extern __shared__ __align__(16) char sm[];
    const int t = threadIdx.x;

    if (blockIdx.x >= CTX_BLOCKS) {
        // ---------------- convert_wout path ----------------
        uint16_t* s_hi = (uint16_t*)sm;                 // [128][66]
        const int cb = blockIdx.x - CTX_BLOCKS;
        const int k0 = (cb & 15) * 64;
        const int n0 = (cb >> 4) * 128;

        for (int it = 0; it < 32; it++) {
            int idx = it * 256 + t;        // 64k x 128n
            int k = idx >> 7, n = idx & 127;
            int gn = n0 + n;
            float v = (gn < VOCAB) ? __ldg(W + (size_t)(k0 + k) * VOCAB + gn) : 0.f;
            s_hi[n * 66 + k] = __half_as_ushort(__float2half_rn(v));
        }
        __syncthreads();
        for (int it = 0; it < 16; it++) {
            int u = it * 256 + t;          // 128 n-rows x 32 uint32
            int nn = u >> 5, ku = (u & 31) * 2;
            uint32_t hv = *(uint32_t*)&s_hi[nn * 66 + ku];
            size_t e = (size_t)(n0 + nn) * HID + k0 + ku;
            *(uint32_t*)((__half*)g_B_hi + e) = hv;
        }
        return;
    }

    // ---------------- fused ctx path: 8 samples ----------------
    float* enh    = (float*)sm;                         // [8][2112]
    float* eo_s   = (float*)(sm + 8*DIN*4);             // [8][256]
    float* logits = (float*)(sm + 8*DIN*4 + 8*256*4);   // [8][8]
    float* mixed  = logits + 8*8;                       // [8][32]

    const int wid = t >> 5, lane = t & 31;
    const int b0 = blockIdx.x * 8;

    // phase 1: each warp handles 1 sample: load row, mean, phasor
    {
        int s = wid;
        const float4* xr = (const float4*)(x + (size_t)(b0 + s) * FEAT);
        float* er = enh + s * DIN;
        float sum = 0.f;
        #pragma unroll 4
        for (int i = lane; i < FEAT/4; i += 32) {
            float4 v = xr[i];
            *(float4*)(er + 4*i) = v;
            sum += (v.x + v.y) + (v.z + v.w);
        }
        #pragma unroll
        for (int o = 16; o > 0; o >>= 1) sum += __shfl_xor_sync(0xffffffffu, sum, o);
        float mean = sum * (1.0f / FEAT);
        float base = 43.98229715025711f * mean;   // 2*pi*7
        float ph = base * (float)(lane + 1);
        er[FEAT + lane]        = cosf(ph);
        er[FEAT + HARM + lane] = sinf(ph);
    }
    __syncthreads();

    // phase 2: 264 dot products of length DIN for 8 samples at once
    for (int jj = t; jj < NEXP + NEXP*EDIM; jj += 256) {
        float acc[8];
        #pragma unroll
        for (int s = 0; s < 8; s++) acc[s] = 0.f;
        const float* wp; long stride;
        if (jj < NEXP) { wp = Wg + jj; stride = NEXP; }
        else { int e = (jj - NEXP) >> 5, h = (jj - NEXP) & 31;
               wp = We + (size_t)e * DIN * EDIM + h; stride = EDIM; }
        for (int d = 0; d < DIN; d += 4) {
            float w0 = wp[(long)(d+0)*stride];
            float w1 = wp[(long)(d+1)*stride];
            float w2 = wp[(long)(d+2)*stride];
            float w3 = wp[(long)(d+3)*stride];
            #pragma unroll
            for (int s = 0; s < 8; s++) {
                float4 ev = *(const float4*)(enh + s*DIN + d);
                float a = acc[s];
                a = fmaf(ev.x, w0, a); a = fmaf(ev.y, w1, a);
                a = fmaf(ev.z, w2, a); a = fmaf(ev.w, w3, a);
                acc[s] = a;
            }
        }
        if (jj < NEXP) {
            #pragma unroll
            for (int s = 0; s < 8; s++) logits[s*8 + jj] = acc[s] + bg[jj];
        } else {
            #pragma unroll
            for (int s = 0; s < 8; s++) eo_s[s*256 + (jj - NEXP)] = acc[s] + be[jj - NEXP];
        }
    }
    __syncthreads();

    // phase 3: softmax per sample
    if (t < 8) {
        float* lg = logits + t*8;
        float mx = lg[0];
        #pragma unroll
        for (int e = 1; e < 8; e++) mx = fmaxf(mx, lg[e]);
        float ss = 0.f;
        #pragma unroll
        for (int e = 0; e < 8; e++) { float ex = expf(lg[e] - mx); lg[e] = ex; ss += ex; }
        float inv = 1.0f / ss;
        #pragma unroll
        for (int e = 0; e < 8; e++) lg[e] *= inv;
    }
    __syncthreads();

    // phase 4: mixed[s][h] (8*32 = 256 = one per thread)
    {
        int s = t >> 5, h = t & 31;
        float m = 0.f;
        #pragma unroll
        for (int e = 0; e < 8; e++) m = fmaf(logits[s*8 + e], eo_s[s*256 + e*32 + h], m);
        mixed[t] = m;
    }
    __syncthreads();

    // phase 5: ctx = tanh(mixed @ Wo + bo)
    for (int it = 0; it < 4; it++) {
        int o = t + it * 256;
        float acc[8];
        float bb = bo[o];
        #pragma unroll
        for (int s = 0; s < 8; s++) acc[s] = bb;
        for (int k = 0; k < EDIM; k++) {
            float w = Wo[(size_t)k * HID + o];
            #pragma unroll
            for (int s = 0; s < 8; s++) acc[s] = fmaf(mixed[s*32 + k], w, acc[s]);
        }
        #pragma unroll
        for (int s = 0; s < 8; s++)
            g_ctx[(size_t)(b0 + s) * HID + o] = tanhf(acc[s]);
    }
}

// ============================================================
// Kernel 2: top-20 of ctx[0,:] -> gain (spiking scan collapses)
// ============================================================
__global__ __launch_bounds__(256) void topk_gain_kernel()
{
    __shared__ float vals[HID];
    __shared__ float rv[256];
    __shared__ int   ri[256];
    const int t = threadIdx.x;
    for (int i = t; i < HID; i += 256) { vals[i] = g_ctx[i]; g_gain[i] = 1.0f; }
    __syncthreads();
    for (int it = 0; it < 20; it++) {
        float best = -1e30f; int bi = 0;
        for (int i = t; i < HID; i += 256)
            if (vals[i] > best) { best = vals[i]; bi = i; }
        rv[t] = best; ri[t] = bi;
        __syncthreads();
        for (int s = 128; s > 0; s >>= 1) {
            if (t < s && rv[t + s] > rv[t]) { rv[t] = rv[t + s]; ri[t] = ri[t + s]; }
            __syncthreads();
        }
        if (t == 0) { g_gain[ri[0]] = 2.0f; vals[ri[0]] = -1e30f; }
        __syncthreads();
    }
}

// ============================================================
// Kernel 3: convert ctx*gain -> fp16, plain [M][K]
// ============================================================
__global__ __launch_bounds__(256) void convert_ctx_kernel()
{
    int idx = blockIdx.x * 256 + threadIdx.x;
    int mr = idx >> 9;
    int k  = (idx & 511) * 2;
    float2 v = *(const float2*)(g_ctx + (size_t)mr * HID + k);
    float2 g = *(const float2*)(g_gain + k);
    __half h0 = __float2half_rn(v.x * g.x);
    __half h1 = __float2half_rn(v.y * g.y);
    uint32_t hi = (uint32_t)__half_as_ushort(h0) | ((uint32_t)__half_as_ushort(h1) << 16);
    *(uint32_t*)((__half*)g_A_hi + (size_t)mr * HID + k) = hi;
}

// ============================================================
// Kernel 4: out = A @ B^T + bias via mma.sync fp16
// CTA 128M x 256N, 512 threads (16 warps of 32x64), BK=64,
// 3-stage cp.async pipeline, ONE sync per chunk.
// ============================================================
#define BK 64
#define SROW 72                        /* fp16 per smem row (pad 8) */
#define ARR_A (128 * SROW * 2)         /* 18432 B */
#define ARR_BN (256 * SROW * 2)        /* 36864 B */
#define STG_B (ARR_A + ARR_BN)         /* 55296 B */
#define NSTG 3
#define NCHUNK (HID / BK)              /* 16 */

__global__ __launch_bounds__(512, 1) void gemm_mma_kernel(
    const float* __restrict__ bias, float* __restrict__ C)
{
    extern __shared__ __align__(16) char sm[];
    const uint32_t sb = smem_u32(sm);
    const int t = threadIdx.x, lane = t & 31, wid = t >> 5;
    const int m0 = blockIdx.x * 128, n0 = blockIdx.y * 256;
    const int m0w = (wid & 3) * 32, n0w = (wid >> 2) * 64;

    float acc[2][8][4];
    #pragma unroll
    for (int i = 0; i < 2; i++)
        #pragma unroll
        for (int j = 0; j < 8; j++)
            #pragma unroll
            for (int q = 0; q < 4; q++) acc[i][j][q] = 0.f;

    const __half* srcA = g_A_hi + (size_t)m0 * HID;
    const __half* srcB = g_B_hi + (size_t)n0 * HID;

    auto issue = [&](int c) {
        uint32_t stg = sb + (uint32_t)(c % NSTG) * STG_B;
        int k0 = c * BK;
        // A: 128 rows x 64 k = 1024 x 16B
        #pragma unroll
        for (int it = 0; it < 2; it++) {
            int idx = it * 512 + t;
            int row = idx >> 3, seg = idx & 7;
            uint32_t d = stg + row * (SROW * 2) + seg * 16;
            CP_ASYNC16(d, srcA + (size_t)row * HID + k0 + seg * 8);
        }
        // B: 256 rows x 64 k = 2048 x 16B
        #pragma unroll
        for (int it = 0; it < 4; it++) {
            int idx = it * 512 + t;
            int row = idx >> 3, seg = idx & 7;
            uint32_t d = stg + ARR_A + row * (SROW * 2) + seg * 16;
            CP_ASYNC16(d, srcB + (size_t)row * HID + k0 + seg * 8);
        }
        CP_COMMIT();
    };

    issue(0); issue(1);
    for (int c = 0; c < NCHUNK; c++) {
        if (c + 1 < NCHUNK) { CP_WAIT1(); } else { CP_WAIT0(); }
        __syncthreads();
        // stage (c+2)%3 was fully consumed at iteration c-1 (fenced above)
        if (c + 2 < NCHUNK) issue(c + 2);

        uint32_t stg = sb + (uint32_t)(c % NSTG) * STG_B;
        uint32_t pAh = stg, pBh = stg + ARR_A;

        #pragma unroll
        for (int ks = 0; ks < 4; ks++) {
            int kb = ks * 16;
            uint32_t acol = (uint32_t)(kb + ((lane >> 4) << 3)) * 2;

            uint32_t ah[2][4];
            #pragma unroll
            for (int mt = 0; mt < 2; mt++) {
                uint32_t ra = (uint32_t)(m0w + mt*16 + (lane & 15)) * (SROW*2) + acol;
                LDSM_X4(ah[mt], pAh + ra);
            }
            // B: 4x ldmatrix.x4, each covers an nt-pair (16 rows x 2 k-halves)
            uint32_t bh[8][2];
            {
                int g = lane >> 3;                 // 0..3
                int browoff = (g & 1) * 8 + (lane & 7);
                int bcoloff = (g >> 1) * 8;
                #pragma unroll
                for (int np = 0; np < 4; np++) {
                    uint32_t r4[4];
                    uint32_t rb = (uint32_t)(n0w + np*16 + browoff) * (SROW*2)
                                + (uint32_t)(kb + bcoloff) * 2;
                    LDSM_X4(r4, pBh + rb);
                    bh[2*np  ][0] = r4[0]; bh[2*np  ][1] = r4[2];
                    bh[2*np+1][0] = r4[1]; bh[2*np+1][1] = r4[3];
                }
            }
            #pragma unroll
            for (int mt = 0; mt < 2; mt++)
                #pragma unroll
                for (int nt = 0; nt < 8; nt++)
                    MMA16816(acc[mt][nt], ah[mt], bh[nt]);
        }
    }

    // ---- epilogue: + bias, store ----
    const bool full = (n0 + 256 <= VOCAB);
    #pragma unroll
    for (int mt = 0; mt < 2; mt++) {
        int r0 = m0 + m0w + mt*16 + (lane >> 2);
        #pragma unroll
        for (int nt = 0; nt < 8; nt++) {
            int cn = n0 + n0w + nt*8 + ((lane & 3) << 1);
            float* c0p = C + (size_t)r0 * VOCAB + cn;
            float* c1p = c0p + (size_t)8 * VOCAB;
            if (full) {
                float b0 = __ldg(bias + cn), b1 = __ldg(bias + cn + 1);
                float v0 = acc[mt][nt][0] + b0, v1 = acc[mt][nt][1] + b1;
                float v2 = acc[mt][nt][2] + b0, v3 = acc[mt][nt][3] + b1;
                if (!(((size_t)r0 * VOCAB + cn) & 1)) {
                    *(float2*)c0p = make_float2(v0, v1);
                } else { c0p[0] = v0; c0p[1] = v1; }
                if (!(((size_t)(r0+8) * VOCAB + cn) & 1)) {
                    *(float2*)c1p = make_float2(v2, v3);
                } else { c1p[0] = v2; c1p[1] = v3; }
            } else {
                if (cn < VOCAB) {
                    float b0 = __ldg(bias + cn);
                    c0p[0] = acc[mt][nt][0] + b0;
                    c1p[0] = acc[mt][nt][2] + b0;
                }
                if (cn + 1 < VOCAB) {
                    float b1 = __ldg(bias + cn + 1);
                    c0p[1] = acc[mt][nt][1] + b1;
                    c1p[1] = acc[mt][nt][3] + b1;
                }
            }
        }
    }
}

// ============================================================
extern "C" void kernel_launch(void* const* d_in, const int* in_sizes, int n_in,
                              void* d_out, int out_size)
{
    const float* x    = (const float*)d_in[0];
    const float* Wg   = (const float*)d_in[1];
    const float* bg   = (const float*)d_in[2];
    const float* We   = (const float*)d_in[3];
    const float* be   = (const float*)d_in[4];
    const float* Wo   = (const float*)d_in[5];
    const float* bo   = (const float*)d_in[6];
    const float* Wout = (const float*)d_in[7];
    const float* bout = (const float*)d_in[8];
    float* out = (float*)d_out;

    const int gemm_smem = NSTG * STG_B;     // 165888
    cudaFuncSetAttribute(prep_kernel,     cudaFuncAttributeMaxDynamicSharedMemorySize, PREP_SMEM);
    cudaFuncSetAttribute(gemm_mma_kernel, cudaFuncAttributeMaxDynamicSharedMemorySize, gemm_smem);

    prep_kernel<<<CTX_BLOCKS + WOUT_BLOCKS, 256, PREP_SMEM>>>(
        x, Wg, bg, We, be, Wo, bo, Wout);
    topk_gain_kernel<<<1, 256>>>();
    convert_ctx_kernel<<<(BATCH*HID/2)/256, 256>>>();
    gemm_mma_kernel<<<dim3(MT128, NT256), 512, gemm_smem>>>(bout, out);
}

// round 10
// speedup vs baseline: 1.0166x; 1.0166x over previous
#include <cuda_runtime.h>
#include <cuda_fp16.h>
#include <math.h>
#include <stdint.h>

#define BATCH 2048
#define FEAT  2048
#define HARM  32
#define DIN   (FEAT + 2*HARM)   /* 2112 */
#define NEXP  8
#define EDIM  32
#define HID   1024
#define VOCAB 50257
#define NPAD  50432             /* 197 * 256 */
#define NT256 197
#define MT128 16

// ---------------- device scratch (no allocations allowed) ----------------
__device__ __align__(16) float  g_ctx[BATCH * HID];          // 8 MB
__device__ __align__(16) float  g_gain[HID];
__device__ __align__(16) __half g_A_hi[BATCH * HID];         // [2048][1024]
__device__ __align__(16) __half g_B_hi[(size_t)NPAD * HID];  // [NPAD][1024] (Wout^T)

__device__ __forceinline__ uint32_t smem_u32(const void* p) {
    uint32_t a;
    asm("{ .reg .u64 t; cvta.to.shared.u64 t, %1; cvt.u32.u64 %0, t; }" : "=r"(a) : "l"(p));
    return a;
}

#define LDSM_X4(r, a) asm volatile( \
    "ldmatrix.sync.aligned.m8n8.x4.shared.b16 {%0,%1,%2,%3}, [%4];" \
    : "=r"((r)[0]),"=r"((r)[1]),"=r"((r)[2]),"=r"((r)[3]) : "r"(a))
#define MMA16816(c, a, b) asm volatile( \
    "mma.sync.aligned.m16n8k16.row.col.f32.f16.f16.f32 " \
    "{%0,%1,%2,%3},{%4,%5,%6,%7},{%8,%9},{%0,%1,%2,%3};" \
    : "+f"((c)[0]),"+f"((c)[1]),"+f"((c)[2]),"+f"((c)[3]) \
    : "r"((a)[0]),"r"((a)[1]),"r"((a)[2]),"r"((a)[3]), "r"((b)[0]),"r"((b)[1]))
#define CP_ASYNC16(d, s) asm volatile( \
    "cp.async.cg.shared.global [%0], [%1], 16;" :: "r"(d), "l"(s) : "memory")
#define CP_COMMIT() asm volatile("cp.async.commit_group;" ::: "memory")
#define CP_WAIT2()  asm volatile("cp.async.wait_group 2;" ::: "memory")
#define CP_WAIT0()  asm volatile("cp.async.wait_group 0;" ::: "memory")

// ============================================================
// Kernel 1: fused ctx — 16 samples per block, 128 blocks
// ============================================================
__global__ __launch_bounds__(256) void fused_ctx_kernel(
    const float* __restrict__ x,
    const float* __restrict__ Wg, const float* __restrict__ bg,
    const float* __restrict__ We, const float* __restrict__ be,
    const float* __restrict__ Wo, const float* __restrict__ bo)
{
    extern __shared__ __align__(16) char sm[];
    float* enh    = (float*)sm;                          // [16][2112]
    float* eo_s   = (float*)(sm + 16*DIN*4);             // [16][256]
    float* logits = (float*)(sm + 16*DIN*4 + 16*256*4);  // [16][8]
    float* mixed  = logits + 16*8;                       // [16][32]

    const int t = threadIdx.x;
    const int wid = t >> 5, lane = t & 31;
    const int b0 = blockIdx.x * 16;

    for (int sh = 0; sh < 2; sh++) {
        int s = wid * 2 + sh;
        const float4* xr = (const float4*)(x + (size_t)(b0 + s) * FEAT);
        float* er = enh + s * DIN;
        float sum = 0.f;
        #pragma unroll 4
        for (int i = lane; i < FEAT/4; i += 32) {
            float4 v = xr[i];
            *(float4*)(er + 4*i) = v;
            sum += (v.x + v.y) + (v.z + v.w);
        }
        #pragma unroll
        for (int o = 16; o > 0; o >>= 1) sum += __shfl_xor_sync(0xffffffffu, sum, o);
        float mean = sum * (1.0f / FEAT);
        float base = 43.98229715025711f * mean;   // 2*pi*7
        float ph = base * (float)(lane + 1);
        er[FEAT + lane]        = cosf(ph);
        er[FEAT + HARM + lane] = sinf(ph);
    }
    __syncthreads();

    for (int jj = t; jj < NEXP + NEXP*EDIM; jj += 256) {
        float acc[16];
        #pragma unroll
        for (int s = 0; s < 16; s++) acc[s] = 0.f;
        const float* wp; long stride;
        if (jj < NEXP) { wp = Wg + jj; stride = NEXP; }
        else { int e = (jj - NEXP) >> 5, h = (jj - NEXP) & 31;
               wp = We + (size_t)e * DIN * EDIM + h; stride = EDIM; }
        for (int d = 0; d < DIN; d += 4) {
            float w0 = wp[(long)(d+0)*stride];
            float w1 = wp[(long)(d+1)*stride];
            float w2 = wp[(long)(d+2)*stride];
            float w3 = wp[(long)(d+3)*stride];
            #pragma unroll
            for (int s = 0; s < 16; s++) {
                float4 ev = *(const float4*)(enh + s*DIN + d);
                float a = acc[s];
                a = fmaf(ev.x, w0, a); a = fmaf(ev.y, w1, a);
                a = fmaf(ev.z, w2, a); a = fmaf(ev.w, w3, a);
                acc[s] = a;
            }
        }
        if (jj < NEXP) {
            #pragma unroll
            for (int s = 0; s < 16; s++) logits[s*8 + jj] = acc[s] + bg[jj];
        } else {
            #pragma unroll
            for (int s = 0; s < 16; s++) eo_s[s*256 + (jj - NEXP)] = acc[s] + be[jj - NEXP];
        }
    }
    __syncthreads();

    if (t < 16) {
        float* lg = logits + t*8;
        float mx = lg[0];
        #pragma unroll
        for (int e = 1; e < 8; e++) mx = fmaxf(mx, lg[e]);
        float ss = 0.f;
        #pragma unroll
        for (int e = 0; e < 8; e++) { float ex = expf(lg[e] - mx); lg[e] = ex; ss += ex; }
        float inv = 1.0f / ss;
        #pragma unroll
        for (int e = 0; e < 8; e++) lg[e] *= inv;
    }
    __syncthreads();

    for (int v = t; v < 16*32; v += 256) {
        int s = v >> 5, h = v & 31;
        float m = 0.f;
        #pragma unroll
        for (int e = 0; e < 8; e++) m = fmaf(logits[s*8 + e], eo_s[s*256 + e*32 + h], m);
        mixed[v] = m;
    }
    __syncthreads();

    for (int it = 0; it < 4; it++) {
        int o = t + it * 256;
        float acc[16];
        float bb = bo[o];
        #pragma unroll
        for (int s = 0; s < 16; s++) acc[s] = bb;
        for (int k = 0; k < EDIM; k++) {
            float w = Wo[(size_t)k * HID + o];
            #pragma unroll
            for (int s = 0; s < 16; s++) acc[s] = fmaf(mixed[s*32 + k], w, acc[s]);
        }
        #pragma unroll
        for (int s = 0; s < 16; s++)
            g_ctx[(size_t)(b0 + s) * HID + o] = tanhf(acc[s]);
    }
}

// ============================================================
// Kernel 2: top-20 of ctx[0,:] -> gain (spiking scan collapses)
// ============================================================
__global__ __launch_bounds__(256) void topk_gain_kernel()
{
    __shared__ float vals[HID];
    __shared__ float rv[256];
    __shared__ int   ri[256];
    const int t = threadIdx.x;
    for (int i = t; i < HID; i += 256) { vals[i] = g_ctx[i]; g_gain[i] = 1.0f; }
    __syncthreads();
    for (int it = 0; it < 20; it++) {
        float best = -1e30f; int bi = 0;
        for (int i = t; i < HID; i += 256)
            if (vals[i] > best) { best = vals[i]; bi = i; }
        rv[t] = best; ri[t] = bi;
        __syncthreads();
        for (int s = 128; s > 0; s >>= 1) {
            if (t < s && rv[t + s] > rv[t]) { rv[t] = rv[t + s]; ri[t] = ri[t + s]; }
            __syncthreads();
        }
        if (t == 0) { g_gain[ri[0]] = 2.0f; vals[ri[0]] = -1e30f; }
        __syncthreads();
    }
}

// ============================================================
// Kernel 3: convert ctx*gain -> fp16, plain [M][K]
// ============================================================
__global__ __launch_bounds__(256) void convert_ctx_kernel()
{
    int idx = blockIdx.x * 256 + threadIdx.x;
    int mr = idx >> 9;
    int k  = (idx & 511) * 2;
    float2 v = *(const float2*)(g_ctx + (size_t)mr * HID + k);
    float2 g = *(const float2*)(g_gain + k);
    __half h0 = __float2half_rn(v.x * g.x);
    __half h1 = __float2half_rn(v.y * g.y);
    uint32_t hi = (uint32_t)__half_as_ushort(h0) | ((uint32_t)__half_as_ushort(h1) << 16);
    *(uint32_t*)((__half*)g_A_hi + (size_t)mr * HID + k) = hi;
}

// ============================================================
// Kernel 4: Wout [K][N] f32 -> g_B_hi [NPAD][K] fp16 (transpose)
// ============================================================
__global__ __launch_bounds__(256) void convert_wout_kernel(const float* __restrict__ W)
{
    __shared__ uint16_t s_hi[128][66];
    const int t = threadIdx.x;
    const int k0 = blockIdx.x * 64;
    const int n0 = blockIdx.y * 128;

    for (int it = 0; it < 32; it++) {
        int idx = it * 256 + t;        // 64k x 128n
        int k = idx >> 7, n = idx & 127;
        int gn = n0 + n;
        float v = (gn < VOCAB) ? __ldg(W + (size_t)(k0 + k) * VOCAB + gn) : 0.f;
        s_hi[n][k] = __half_as_ushort(__float2half_rn(v));
    }
    __syncthreads();

    for (int it = 0; it < 16; it++) {
        int u = it * 256 + t;          // 128 n-rows x 32 uint32
        int nn = u >> 5, ku = (u & 31) * 2;
        uint32_t hv = *(uint32_t*)&s_hi[nn][ku];
        size_t e = (size_t)(n0 + nn) * HID + k0 + ku;
        *(uint32_t*)((__half*)g_B_hi + e) = hv;
    }
}

// ============================================================
// Kernel 5: out = A @ B^T + bias via mma.sync fp16
// CTA 128M x 256N, 512 threads (16 warps of 32x64), BK=64,
// 4-stage cp.async pipeline, ONE sync per chunk.
// ============================================================
#define BK 64
#define SROW 72                        /* fp16 per smem row (pad 8) */
#define ARR_A (128 * SROW * 2)         /* 18432 B */
#define ARR_BN (256 * SROW * 2)        /* 36864 B */
#define STG_B (ARR_A + ARR_BN)         /* 55296 B */
#define NSTG 4
#define NCHUNK (HID / BK)              /* 16 */

__global__ __launch_bounds__(512, 1) void gemm_mma_kernel(
    const float* __restrict__ bias, float* __restrict__ C)
{
    extern __shared__ __align__(16) char sm[];
    const uint32_t sb = smem_u32(sm);
    const int t = threadIdx.x, lane = t & 31, wid = t >> 5;
    const int m0 = blockIdx.x * 128, n0 = blockIdx.y * 256;
    const int m0w = (wid & 3) * 32, n0w = (wid >> 2) * 64;

    float acc[2][8][4];
    #pragma unroll
    for (int i = 0; i < 2; i++)
        #pragma unroll
        for (int j = 0; j < 8; j++)
            #pragma unroll
            for (int q = 0; q < 4; q++) acc[i][j][q] = 0.f;

    const __half* srcA = g_A_hi + (size_t)m0 * HID;
    const __half* srcB = g_B_hi + (size_t)n0 * HID;

    auto issue = [&](int c) {
        uint32_t stg = sb + (uint32_t)(c & (NSTG - 1)) * STG_B;
        int k0 = c * BK;
        // A: 128 rows x 64 k = 1024 x 16B
        #pragma unroll
        for (int it = 0; it < 2; it++) {
            int idx = it * 512 + t;
            int row = idx >> 3, seg = idx & 7;
            uint32_t d = stg + row * (SROW * 2) + seg * 16;
            CP_ASYNC16(d, srcA + (size_t)row * HID + k0 + seg * 8);
        }
        // B: 256 rows x 64 k = 2048 x 16B
        #pragma unroll
        for (int it = 0; it < 4; it++) {
            int idx = it * 512 + t;
            int row = idx >> 3, seg = idx & 7;
            uint32_t d = stg + ARR_A + row * (SROW * 2) + seg * 16;
            CP_ASYNC16(d, srcB + (size_t)row * HID + k0 + seg * 8);
        }
        CP_COMMIT();
    };

    issue(0); issue(1); issue(2);
    for (int c = 0; c < NCHUNK; c++) {
        if (c + 2 < NCHUNK) { CP_WAIT2(); } else { CP_WAIT0(); }
        __syncthreads();
        // stage (c+3)%4 was fully consumed at iteration c-1 (fenced above)
        if (c + 3 < NCHUNK) issue(c + 3);

        uint32_t stg = sb + (uint32_t)(c & (NSTG - 1)) * STG_B;
        uint32_t pAh = stg, pBh = stg + ARR_A;

        #pragma unroll
        for (int ks = 0; ks < 4; ks++) {
            int kb = ks * 16;
            uint32_t acol = (uint32_t)(kb + ((lane >> 4) << 3)) * 2;

            uint32_t ah[2][4];
            #pragma unroll
            for (int mt = 0; mt < 2; mt++) {
                uint32_t ra = (uint32_t)(m0w + mt*16 + (lane & 15)) * (SROW*2) + acol;
                LDSM_X4(ah[mt], pAh + ra);
            }
            // B: 4x ldmatrix.x4, each covers an nt-pair (16 rows x 2 k-halves)
            uint32_t bh[8][2];
            {
                int g = lane >> 3;                 // 0..3
                int browoff = (g & 1) * 8 + (lane & 7);
                int bcoloff = (g >> 1) * 8;
                #pragma unroll
                for (int np = 0; np < 4; np++) {
                    uint32_t r4[4];
                    uint32_t rb = (uint32_t)(n0w + np*16 + browoff) * (SROW*2)
                                + (uint32_t)(kb + bcoloff) * 2;
                    LDSM_X4(r4, pBh + rb);
                    bh[2*np  ][0] = r4[0]; bh[2*np  ][1] = r4[2];
                    bh[2*np+1][0] = r4[1]; bh[2*np+1][1] = r4[3];
                }
            }
            #pragma unroll
            for (int mt = 0; mt < 2; mt++)
                #pragma unroll
                for (int nt = 0; nt < 8; nt++)
                    MMA16816(acc[mt][nt], ah[mt], bh[nt]);
        }
    }

    // ---- epilogue: + bias, store ----
    const bool full = (n0 + 256 <= VOCAB);
    #pragma unroll
    for (int mt = 0; mt < 2; mt++) {
        int r0 = m0 + m0w + mt*16 + (lane >> 2);
        #pragma unroll
        for (int nt = 0; nt < 8; nt++) {
            int cn = n0 + n0w + nt*8 + ((lane & 3) << 1);
            float* c0p = C + (size_t)r0 * VOCAB + cn;
            float* c1p = c0p + (size_t)8 * VOCAB;
            if (full) {
                float b0 = __ldg(bias + cn), b1 = __ldg(bias + cn + 1);
                float v0 = acc[mt][nt][0] + b0, v1 = acc[mt][nt][1] + b1;
                float v2 = acc[mt][nt][2] + b0, v3 = acc[mt][nt][3] + b1;
                if (!(((size_t)r0 * VOCAB + cn) & 1)) {
                    *(float2*)c0p = make_float2(v0, v1);
                } else { c0p[0] = v0; c0p[1] = v1; }
                if (!(((size_t)(r0+8) * VOCAB + cn) & 1)) {
                    *(float2*)c1p = make_float2(v2, v3);
                } else { c1p[0] = v2; c1p[1] = v3; }
            } else {
                if (cn < VOCAB) {
                    float b0 = __ldg(bias + cn);
                    c0p[0] = acc[mt][nt][0] + b0;
                    c1p[0] = acc[mt][nt][2] + b0;
                }
                if (cn + 1 < VOCAB) {
                    float b1 = __ldg(bias + cn + 1);
                    c0p[1] = acc[mt][nt][1] + b1;
                    c1p[1] = acc[mt][nt][3] + b1;
                }
            }
        }
    }
}

// ============================================================
extern "C" void kernel_launch(void* const* d_in, const int* in_sizes, int n_in,
                              void* d_out, int out_size)
{
    const float* x    = (const float*)d_in[0];
    const float* Wg   = (const float*)d_in[1];
    const float* bg   = (const float*)d_in[2];
    const float* We   = (const float*)d_in[3];
    const float* be   = (const float*)d_in[4];
    const float* Wo   = (const float*)d_in[5];
    const float* bo   = (const float*)d_in[6];
    const float* Wout = (const float*)d_in[7];
    const float* bout = (const float*)d_in[8];
    float* out = (float*)d_out;

    const int ctx_smem  = 16*DIN*4 + 16*256*4 + 16*8*4 + 16*32*4;   // 154112
    const int gemm_smem = NSTG * STG_B;                              // 221184
    cudaFuncSetAttribute(fused_ctx_kernel, cudaFuncAttributeMaxDynamicSharedMemorySize, ctx_smem);
    cudaFuncSetAttribute(gemm_mma_kernel,  cudaFuncAttributeMaxDynamicSharedMemorySize, gemm_smem);

    convert_wout_kernel<<<dim3(16, 394), 256>>>(Wout);
    fused_ctx_kernel<<<BATCH/16, 256, ctx_smem>>>(x, Wg, bg, We, be, Wo, bo);
    topk_gain_kernel<<<1, 256>>>();
    convert_ctx_kernel<<<(BATCH*HID/2)/256, 256>>>();
    gemm_mma_kernel<<<dim3(MT128, NT256), 512, gemm_smem>>>(bout, out);
}

// round 11
// speedup vs baseline: 1.0184x; 1.0017x over previous
#include <cuda_runtime.h>
#include <cuda_fp16.h>
#include <math.h>
#include <stdint.h>

#define BATCH 2048
#define FEAT  2048
#define HARM  32
#define DIN   (FEAT + 2*HARM)   /* 2112 */
#define NEXP  8
#define EDIM  32
#define HID   1024
#define VOCAB 50257
#define NPAD  50432             /* 197 * 256 */
#define NT256 197
#define MT128 16

// ---------------- device scratch (no allocations allowed) ----------------
__device__ __align__(16) float  g_ctx[BATCH * HID];          // 8 MB
__device__ __align__(16) float  g_gain[HID];
__device__ __align__(16) __half g_A_hi[BATCH * HID];         // [2048][1024]
__device__ __align__(16) __half g_B_hi[(size_t)NPAD * HID];  // [NPAD][1024] (Wout^T)

__device__ __forceinline__ uint32_t smem_u32(const void* p) {
    uint32_t a;
    asm("{ .reg .u64 t; cvta.to.shared.u64 t, %1; cvt.u32.u64 %0, t; }" : "=r"(a) : "l"(p));
    return a;
}

#define LDSM_X4(r, a) asm volatile( \
    "ldmatrix.sync.aligned.m8n8.x4.shared.b16 {%0,%1,%2,%3}, [%4];" \
    : "=r"((r)[0]),"=r"((r)[1]),"=r"((r)[2]),"=r"((r)[3]) : "r"(a))
#define MMA16816(c, a, b) asm volatile( \
    "mma.sync.aligned.m16n8k16.row.col.f32.f16.f16.f32 " \
    "{%0,%1,%2,%3},{%4,%5,%6,%7},{%8,%9},{%0,%1,%2,%3};" \
    : "+f"((c)[0]),"+f"((c)[1]),"+f"((c)[2]),"+f"((c)[3]) \
    : "r"((a)[0]),"r"((a)[1]),"r"((a)[2]),"r"((a)[3]), "r"((b)[0]),"r"((b)[1]))
#define CP_ASYNC16(d, s) asm volatile( \
    "cp.async.cg.shared.global [%0], [%1], 16;" :: "r"(d), "l"(s) : "memory")
#define CP_COMMIT() asm volatile("cp.async.commit_group;" ::: "memory")
#define CP_WAIT1()  asm volatile("cp.async.wait_group 1;" ::: "memory")
#define CP_WAIT0()  asm volatile("cp.async.wait_group 0;" ::: "memory")

// ============================================================
// Kernel 1: fused ctx — 16 samples per block, 128 blocks
// ============================================================
__global__ __launch_bounds__(256) void fused_ctx_kernel(
    const float* __restrict__ x,
    const float* __restrict__ Wg, const float* __restrict__ bg,
    const float* __restrict__ We, const float* __restrict__ be,
    const float* __restrict__ Wo, const float* __restrict__ bo)
{
    extern __shared__ __align__(16) char sm[];
    float* enh    = (float*)sm;                          // [16][2112]
    float* eo_s   = (float*)(sm + 16*DIN*4);             // [16][256]
    float* logits = (float*)(sm + 16*DIN*4 + 16*256*4);  // [16][8]
    float* mixed  = logits + 16*8;                       // [16][32]

    const int t = threadIdx.x;
    const int wid = t >> 5, lane = t & 31;
    const int b0 = blockIdx.x * 16;

    for (int sh = 0; sh < 2; sh++) {
        int s = wid * 2 + sh;
        const float4* xr = (const float4*)(x + (size_t)(b0 + s) * FEAT);
        float* er = enh + s * DIN;
        float sum = 0.f;
        #pragma unroll 4
        for (int i = lane; i < FEAT/4; i += 32) {
            float4 v = xr[i];
            *(float4*)(er + 4*i) = v;
            sum += (v.x + v.y) + (v.z + v.w);
        }
        #pragma unroll
        for (int o = 16; o > 0; o >>= 1) sum += __shfl_xor_sync(0xffffffffu, sum, o);
        float mean = sum * (1.0f / FEAT);
        float base = 43.98229715025711f * mean;   // 2*pi*7
        float ph = base * (float)(lane + 1);
        er[FEAT + lane]        = cosf(ph);
        er[FEAT + HARM + lane] = sinf(ph);
    }
    __syncthreads();

    for (int jj = t; jj < NEXP + NEXP*EDIM; jj += 256) {
        float acc[16];
        #pragma unroll
        for (int s = 0; s < 16; s++) acc[s] = 0.f;
        const float* wp; long stride;
        if (jj < NEXP) { wp = Wg + jj; stride = NEXP; }
        else { int e = (jj - NEXP) >> 5, h = (jj - NEXP) & 31;
               wp = We + (size_t)e * DIN * EDIM + h; stride = EDIM; }
        for (int d = 0; d < DIN; d += 4) {
            float w0 = wp[(long)(d+0)*stride];
            float w1 = wp[(long)(d+1)*stride];
            float w2 = wp[(long)(d+2)*stride];
            float w3 = wp[(long)(d+3)*stride];
            #pragma unroll
            for (int s = 0; s < 16; s++) {
                float4 ev = *(const float4*)(enh + s*DIN + d);
                float a = acc[s];
                a = fmaf(ev.x, w0, a); a = fmaf(ev.y, w1, a);
                a = fmaf(ev.z, w2, a); a = fmaf(ev.w, w3, a);
                acc[s] = a;
            }
        }
        if (jj < NEXP) {
            #pragma unroll
            for (int s = 0; s < 16; s++) logits[s*8 + jj] = acc[s] + bg[jj];
        } else {
            #pragma unroll
            for (int s = 0; s < 16; s++) eo_s[s*256 + (jj - NEXP)] = acc[s] + be[jj - NEXP];
        }
    }
    __syncthreads();

    if (t < 16) {
        float* lg = logits + t*8;
        float mx = lg[0];
        #pragma unroll
        for (int e = 1; e < 8; e++) mx = fmaxf(mx, lg[e]);
        float ss = 0.f;
        #pragma unroll
        for (int e = 0; e < 8; e++) { float ex = expf(lg[e] - mx); lg[e] = ex; ss += ex; }
        float inv = 1.0f / ss;
        #pragma unroll
        for (int e = 0; e < 8; e++) lg[e] *= inv;
    }
    __syncthreads();

    for (int v = t; v < 16*32; v += 256) {
        int s = v >> 5, h = v & 31;
        float m = 0.f;
        #pragma unroll
        for (int e = 0; e < 8; e++) m = fmaf(logits[s*8 + e], eo_s[s*256 + e*32 + h], m);
        mixed[v] = m;
    }
    __syncthreads();

    for (int it = 0; it < 4; it++) {
        int o = t + it * 256;
        float acc[16];
        float bb = bo[o];
        #pragma unroll
        for (int s = 0; s < 16; s++) acc[s] = bb;
        for (int k = 0; k < EDIM; k++) {
            float w = Wo[(size_t)k * HID + o];
            #pragma unroll
            for (int s = 0; s < 16; s++) acc[s] = fmaf(mixed[s*32 + k], w, acc[s]);
        }
        #pragma unroll
        for (int s = 0; s < 16; s++)
            g_ctx[(size_t)(b0 + s) * HID + o] = tanhf(acc[s]);
    }
}

// ============================================================
// Kernel 2: top-20 of ctx[0,:] -> gain (spiking scan collapses)
// ============================================================
__global__ __launch_bounds__(256) void topk_gain_kernel()
{
    __shared__ float vals[HID];
    __shared__ float rv[256];
    __shared__ int   ri[256];
    const int t = threadIdx.x;
    for (int i = t; i < HID; i += 256) { vals[i] = g_ctx[i]; g_gain[i] = 1.0f; }
    __syncthreads();
    for (int it = 0; it < 20; it++) {
        float best = -1e30f; int bi = 0;
        for (int i = t; i < HID; i += 256)
            if (vals[i] > best) { best = vals[i]; bi = i; }
        rv[t] = best; ri[t] = bi;
        __syncthreads();
        for (int s = 128; s > 0; s >>= 1) {
            if (t < s && rv[t + s] > rv[t]) { rv[t] = rv[t + s]; ri[t] = ri[t + s]; }
            __syncthreads();
        }
        if (t == 0) { g_gain[ri[0]] = 2.0f; vals[ri[0]] = -1e30f; }
        __syncthreads();
    }
}

// ============================================================
// Kernel 3: convert ctx*gain -> fp16, plain [M][K]
// ============================================================
__global__ __launch_bounds__(256) void convert_ctx_kernel()
{
    int idx = blockIdx.x * 256 + threadIdx.x;
    int mr = idx >> 9;
    int k  = (idx & 511) * 2;
    float2 v = *(const float2*)(g_ctx + (size_t)mr * HID + k);
    float2 g = *(const float2*)(g_gain + k);
    __half h0 = __float2half_rn(v.x * g.x);
    __half h1 = __float2half_rn(v.y * g.y);
    uint32_t hi = (uint32_t)__half_as_ushort(h0) | ((uint32_t)__half_as_ushort(h1) << 16);
    *(uint32_t*)((__half*)g_A_hi + (size_t)mr * HID + k) = hi;
}

// ============================================================
// Kernel 4: Wout [K][N] f32 -> g_B_hi [NPAD][K] fp16 (transpose)
// ============================================================
__global__ __launch_bounds__(256) void convert_wout_kernel(const float* __restrict__ W)
{
    __shared__ uint16_t s_hi[128][66];
    const int t = threadIdx.x;
    const int k0 = blockIdx.x * 64;
    const int n0 = blockIdx.y * 128;

    for (int it = 0; it < 32; it++) {
        int idx = it * 256 + t;        // 64k x 128n
        int k = idx >> 7, n = idx & 127;
        int gn = n0 + n;
        float v = (gn < VOCAB) ? __ldg(W + (size_t)(k0 + k) * VOCAB + gn) : 0.f;
        s_hi[n][k] = __half_as_ushort(__float2half_rn(v));
    }
    __syncthreads();

    for (int it = 0; it < 16; it++) {
        int u = it * 256 + t;          // 128 n-rows x 32 uint32
        int nn = u >> 5, ku = (u & 31) * 2;
        uint32_t hv = *(uint32_t*)&s_hi[nn][ku];
        size_t e = (size_t)(n0 + nn) * HID + k0 + ku;
        *(uint32_t*)((__half*)g_B_hi + e) = hv;
    }
}

// ============================================================
// Kernel 5: out = A @ B^T + bias via mma.sync fp16
// CTA 128M x 256N, 512 threads (16 warps of 32x64), BK=64,
// 3-stage cp.async pipeline (166KB smem keeps 62KB of L1 for
// the cp.async/texture path — 4 stages measurably regressed).
// ============================================================
#define BK 64
#define SROW 72                        /* fp16 per smem row (pad 8) */
#define ARR_A (128 * SROW * 2)         /* 18432 B */
#define ARR_BN (256 * SROW * 2)        /* 36864 B */
#define STG_B (ARR_A + ARR_BN)         /* 55296 B */
#define NSTG 3
#define NCHUNK (HID / BK)              /* 16 */

__global__ __launch_bounds__(512, 1) void gemm_mma_kernel(
    const float* __restrict__ bias, float* __restrict__ C)
{
    extern __shared__ __align__(16) char sm[];
    const uint32_t sb = smem_u32(sm);
    const int t = threadIdx.x, lane = t & 31, wid = t >> 5;
    const int m0 = blockIdx.x * 128, n0 = blockIdx.y * 256;
    const int m0w = (wid & 3) * 32, n0w = (wid >> 2) * 64;

    float acc[2][8][4];
    #pragma unroll
    for (int i = 0; i < 2; i++)
        #pragma unroll
        for (int j = 0; j < 8; j++)
            #pragma unroll
            for (int q = 0; q < 4; q++) acc[i][j][q] = 0.f;

    const __half* srcA = g_A_hi + (size_t)m0 * HID;
    const __half* srcB = g_B_hi + (size_t)n0 * HID;

    auto issue = [&](int c) {
        uint32_t stg = sb + (uint32_t)(c % NSTG) * STG_B;
        int k0 = c * BK;
        // A: 128 rows x 64 k = 1024 x 16B
        #pragma unroll
        for (int it = 0; it < 2; it++) {
            int idx = it * 512 + t;
            int row = idx >> 3, seg = idx & 7;
            uint32_t d = stg + row * (SROW * 2) + seg * 16;
            CP_ASYNC16(d, srcA + (size_t)row * HID + k0 + seg * 8);
        }
        // B: 256 rows x 64 k = 2048 x 16B
        #pragma unroll
        for (int it = 0; it < 4; it++) {
            int idx = it * 512 + t;
            int row = idx >> 3, seg = idx & 7;
            uint32_t d = stg + ARR_A + row * (SROW * 2) + seg * 16;
            CP_ASYNC16(d, srcB + (size_t)row * HID + k0 + seg * 8);
        }
        CP_COMMIT();
    };

    issue(0); issue(1);
    for (int c = 0; c < NCHUNK; c++) {
        if (c + 1 < NCHUNK) { CP_WAIT1(); } else { CP_WAIT0(); }
        __syncthreads();
        // stage (c+2)%3 was fully consumed at iteration c-1 (fenced above)
        if (c + 2 < NCHUNK) issue(c + 2);

        uint32_t stg = sb + (uint32_t)(c % NSTG) * STG_B;
        uint32_t pAh = stg, pBh = stg + ARR_A;

        #pragma unroll
        for (int ks = 0; ks < 4; ks++) {
            int kb = ks * 16;
            uint32_t acol = (uint32_t)(kb + ((lane >> 4) << 3)) * 2;

            uint32_t ah[2][4];
            #pragma unroll
            for (int mt = 0; mt < 2; mt++) {
                uint32_t ra = (uint32_t)(m0w + mt*16 + (lane & 15)) * (SROW*2) + acol;
                LDSM_X4(ah[mt], pAh + ra);
            }
            // B: 4x ldmatrix.x4, each covers an nt-pair (16 rows x 2 k-halves)
            uint32_t bh[8][2];
            {
                int g = lane >> 3;                 // 0..3
                int browoff = (g & 1) * 8 + (lane & 7);
                int bcoloff = (g >> 1) * 8;
                #pragma unroll
                for (int np = 0; np < 4; np++) {
                    uint32_t r4[4];
                    uint32_t rb = (uint32_t)(n0w + np*16 + browoff) * (SROW*2)
                                + (uint32_t)(kb + bcoloff) * 2;
                    LDSM_X4(r4, pBh + rb);
                    bh[2*np  ][0] = r4[0]; bh[2*np  ][1] = r4[2];
                    bh[2*np+1][0] = r4[1]; bh[2*np+1][1] = r4[3];
                }
            }
            #pragma unroll
            for (int mt = 0; mt < 2; mt++)
                #pragma unroll
                for (int nt = 0; nt < 8; nt++)
                    MMA16816(acc[mt][nt], ah[mt], bh[nt]);
        }
    }

    // ---- epilogue: + bias, store ----
    const bool full = (n0 + 256 <= VOCAB);
    #pragma unroll
    for (int mt = 0; mt < 2; mt++) {
        int r0 = m0 + m0w + mt*16 + (lane >> 2);
        #pragma unroll
        for (int nt = 0; nt < 8; nt++) {
            int cn = n0 + n0w + nt*8 + ((lane & 3) << 1);
            float* c0p = C + (size_t)r0 * VOCAB + cn;
            float* c1p = c0p + (size_t)8 * VOCAB;
            if (full) {
                float b0 = __ldg(bias + cn), b1 = __ldg(bias + cn + 1);
                float v0 = acc[mt][nt][0] + b0, v1 = acc[mt][nt][1] + b1;
                float v2 = acc[mt][nt][2] + b0, v3 = acc[mt][nt][3] + b1;
                if (!(((size_t)r0 * VOCAB + cn) & 1)) {
                    *(float2*)c0p = make_float2(v0, v1);
                } else { c0p[0] = v0; c0p[1] = v1; }
                if (!(((size_t)(r0+8) * VOCAB + cn) & 1)) {
                    *(float2*)c1p = make_float2(v2, v3);
                } else { c1p[0] = v2; c1p[1] = v3; }
            } else {
                if (cn < VOCAB) {
                    float b0 = __ldg(bias + cn);
                    c0p[0] = acc[mt][nt][0] + b0;
                    c1p[0] = acc[mt][nt][2] + b0;
                }
                if (cn + 1 < VOCAB) {
                    float b1 = __ldg(bias + cn + 1);
                    c0p[1] = acc[mt][nt][1] + b1;
                    c1p[1] = acc[mt][nt][3] + b1;
                }
            }
        }
    }
}

// ============================================================
extern "C" void kernel_launch(void* const* d_in, const int* in_sizes, int n_in,
                              void* d_out, int out_size)
{
    const float* x    = (const float*)d_in[0];
    const float* Wg   = (const float*)d_in[1];
    const float* bg   = (const float*)d_in[2];
    const float* We   = (const float*)d_in[3];
    const float* be   = (const float*)d_in[4];
    const float* Wo   = (const float*)d_in[5];
    const float* bo   = (const float*)d_in[6];
    const float* Wout = (const float*)d_in[7];
    const float* bout = (const float*)d_in[8];
    float* out = (float*)d_out;

    const int ctx_smem  = 16*DIN*4 + 16*256*4 + 16*8*4 + 16*32*4;   // 154112
    const int gemm_smem = NSTG * STG_B;                              // 165888
    cudaFuncSetAttribute(fused_ctx_kernel, cudaFuncAttributeMaxDynamicSharedMemorySize, ctx_smem);
    cudaFuncSetAttribute(gemm_mma_kernel,  cudaFuncAttributeMaxDynamicSharedMemorySize, gemm_smem);

    convert_wout_kernel<<<dim3(16, 394), 256>>>(Wout);
    fused_ctx_kernel<<<BATCH/16, 256, ctx_smem>>>(x, Wg, bg, We, be, Wo, bo);
    topk_gain_kernel<<<1, 256>>>();
    convert_ctx_kernel<<<(BATCH*HID/2)/256, 256>>>();
    gemm_mma_kernel<<<dim3(MT128, NT256), 512, gemm_smem>>>(bout, out);
}

// round 12
// speedup vs baseline: 1.2274x; 1.2053x over previous
#include <cuda_runtime.h>
#include <cuda_fp16.h>
#include <math.h>
#include <stdint.h>

#define BATCH 2048
#define FEAT  2048
#define HARM  32
#define DIN   (FEAT + 2*HARM)   /* 2112 */
#define NEXP  8
#define EDIM  32
#define HID   1024
#define VOCAB 50257
#define NPAD  50432
#define NT128 394
#define MT128 16

// ---------------- device scratch (no allocations allowed) ----------------
__device__ __align__(16) float  g_ctx[BATCH * HID];          // 8 MB
__device__ __align__(16) float  g_gain[HID];
__device__ __align__(16) __half g_A_hi[BATCH * HID];         // [2048][1024]
__device__ __align__(16) __half g_B_hi[(size_t)NPAD * HID];  // [NPAD][1024] (Wout^T)

__device__ __forceinline__ uint32_t smem_u32(const void* p) {
    uint32_t a;
    asm("{ .reg .u64 t; cvta.to.shared.u64 t, %1; cvt.u32.u64 %0, t; }" : "=r"(a) : "l"(p));
    return a;
}

#define LDSM_X4(r, a) asm volatile( \
    "ldmatrix.sync.aligned.m8n8.x4.shared.b16 {%0,%1,%2,%3}, [%4];" \
    : "=r"((r)[0]),"=r"((r)[1]),"=r"((r)[2]),"=r"((r)[3]) : "r"(a))
#define MMA16816(c, a, b) asm volatile( \
    "mma.sync.aligned.m16n8k16.row.col.f32.f16.f16.f32 " \
    "{%0,%1,%2,%3},{%4,%5,%6,%7},{%8,%9},{%0,%1,%2,%3};" \
    : "+f"((c)[0]),"+f"((c)[1]),"+f"((c)[2]),"+f"((c)[3]) \
    : "r"((a)[0]),"r"((a)[1]),"r"((a)[2]),"r"((a)[3]), "r"((b)[0]),"r"((b)[1]))
#define CP_ASYNC16(d, s) asm volatile( \
    "cp.async.cg.shared.global [%0], [%1], 16;" :: "r"(d), "l"(s) : "memory")
#define CP_COMMIT() asm volatile("cp.async.commit_group;" ::: "memory")
#define CP_WAIT1()  asm volatile("cp.async.wait_group 1;" ::: "memory")
#define CP_WAIT0()  asm volatile("cp.async.wait_group 0;" ::: "memory")

// ============================================================
// Kernel 1: fused ctx — 16 samples per block, 128 blocks.
// Phase 2 rebuilt: 256 expert outputs = 1 per thread (uniform),
// 8 gate logits via per-warp shuffle reductions (no straggler pass,
// no Wg/We divergence inside a warp).
// ============================================================
__global__ __launch_bounds__(256) void fused_ctx_kernel(
    const float* __restrict__ x,
    const float* __restrict__ Wg, const float* __restrict__ bg,
    const float* __restrict__ We, const float* __restrict__ be,
    const float* __restrict__ Wo, const float* __restrict__ bo)
{
    extern __shared__ __align__(16) char sm[];
    float* enh    = (float*)sm;                          // [16][2112]
    float* eo_s   = (float*)(sm + 16*DIN*4);             // [16][256]
    float* logits = (float*)(sm + 16*DIN*4 + 16*256*4);  // [16][8]
    float* mixed  = logits + 16*8;                       // [16][32]

    const int t = threadIdx.x;
    const int wid = t >> 5, lane = t & 31;
    const int b0 = blockIdx.x * 16;

    // phase 1: each warp handles 2 samples: load row, mean, phasor
    for (int sh = 0; sh < 2; sh++) {
        int s = wid * 2 + sh;
        const float4* xr = (const float4*)(x + (size_t)(b0 + s) * FEAT);
        float* er = enh + s * DIN;
        float sum = 0.f;
        #pragma unroll 4
        for (int i = lane; i < FEAT/4; i += 32) {
            float4 v = xr[i];
            *(float4*)(er + 4*i) = v;
            sum += (v.x + v.y) + (v.z + v.w);
        }
        #pragma unroll
        for (int o = 16; o > 0; o >>= 1) sum += __shfl_xor_sync(0xffffffffu, sum, o);
        float mean = sum * (1.0f / FEAT);
        float base = 43.98229715025711f * mean;   // 2*pi*7
        float ph = base * (float)(lane + 1);
        er[FEAT + lane]        = cosf(ph);
        er[FEAT + HARM + lane] = sinf(ph);
    }
    __syncthreads();

    // phase 2a: 256 expert outputs, exactly one per thread
    {
        const int e = t >> 5, h = t & 31;
        const float* wp = We + (size_t)e * DIN * EDIM + h;
        float acc[16];
        #pragma unroll
        for (int s = 0; s < 16; s++) acc[s] = 0.f;
        for (int d = 0; d < DIN; d += 4) {
            float w0 = wp[(size_t)(d+0) * EDIM];
            float w1 = wp[(size_t)(d+1) * EDIM];
            float w2 = wp[(size_t)(d+2) * EDIM];
            float w3 = wp[(size_t)(d+3) * EDIM];
            #pragma unroll
            for (int s = 0; s < 16; s++) {
                float4 ev = *(const float4*)(enh + s*DIN + d);
                float a = acc[s];
                a = fmaf(ev.x, w0, a); a = fmaf(ev.y, w1, a);
                a = fmaf(ev.z, w2, a); a = fmaf(ev.w, w3, a);
                acc[s] = a;
            }
        }
        #pragma unroll
        for (int s = 0; s < 16; s++) eo_s[s*256 + t] = acc[s] + be[t];
    }

    // phase 2b: 8 gate logits, one per warp, shuffle-reduced over DIN
    {
        const int e = wid;                  // gate column
        float acc[16];
        #pragma unroll
        for (int s = 0; s < 16; s++) acc[s] = 0.f;
        for (int d = lane; d < DIN; d += 32) {
            float w = Wg[(size_t)d * NEXP + e];
            #pragma unroll
            for (int s = 0; s < 16; s++)
                acc[s] = fmaf(enh[s*DIN + d], w, acc[s]);
        }
        #pragma unroll
        for (int s = 0; s < 16; s++) {
            float v = acc[s];
            #pragma unroll
            for (int o = 16; o > 0; o >>= 1) v += __shfl_xor_sync(0xffffffffu, v, o);
            if (lane == 0) logits[s*8 + e] = v + bg[e];
        }
    }
    __syncthreads();

    // phase 3: softmax per sample
    if (t < 16) {
        float* lg = logits + t*8;
        float mx = lg[0];
        #pragma unroll
        for (int e = 1; e < 8; e++) mx = fmaxf(mx, lg[e]);
        float ss = 0.f;
        #pragma unroll
        for (int e = 0; e < 8; e++) { float ex = expf(lg[e] - mx); lg[e] = ex; ss += ex; }
        float inv = 1.0f / ss;
        #pragma unroll
        for (int e = 0; e < 8; e++) lg[e] *= inv;
    }
    __syncthreads();

    // phase 4: mixed
    for (int v = t; v < 16*32; v += 256) {
        int s = v >> 5, h = v & 31;
        float m = 0.f;
        #pragma unroll
        for (int e = 0; e < 8; e++) m = fmaf(logits[s*8 + e], eo_s[s*256 + e*32 + h], m);
        mixed[v] = m;
    }
    __syncthreads();

    // phase 5: ctx = tanh(mixed @ Wo + bo)
    for (int it = 0; it < 4; it++) {
        int o = t + it * 256;
        float acc[16];
        float bb = bo[o];
        #pragma unroll
        for (int s = 0; s < 16; s++) acc[s] = bb;
        for (int k = 0; k < EDIM; k++) {
            float w = Wo[(size_t)k * HID + o];
            #pragma unroll
            for (int s = 0; s < 16; s++) acc[s] = fmaf(mixed[s*32 + k], w, acc[s]);
        }
        #pragma unroll
        for (int s = 0; s < 16; s++)
            g_ctx[(size_t)(b0 + s) * HID + o] = tanhf(acc[s]);
    }
}

// ============================================================
// Kernel 2: top-20 of ctx[0,:] -> gain (spiking scan collapses)
// ============================================================
__global__ __launch_bounds__(256) void topk_gain_kernel()
{
    __shared__ float vals[HID];
    __shared__ float rv[256];
    __shared__ int   ri[256];
    const int t = threadIdx.x;
    for (int i = t; i < HID; i += 256) { vals[i] = g_ctx[i]; g_gain[i] = 1.0f; }
    __syncthreads();
    for (int it = 0; it < 20; it++) {
        float best = -1e30f; int bi = 0;
        for (int i = t; i < HID; i += 256)
            if (vals[i] > best) { best = vals[i]; bi = i; }
        rv[t] = best; ri[t] = bi;
        __syncthreads();
        for (int s = 128; s > 0; s >>= 1) {
            if (t < s && rv[t + s] > rv[t]) { rv[t] = rv[t + s]; ri[t] = ri[t + s]; }
            __syncthreads();
        }
        if (t == 0) { g_gain[ri[0]] = 2.0f; vals[ri[0]] = -1e30f; }
        __syncthreads();
    }
}

// ============================================================
// Kernel 3: convert ctx*gain -> fp16, plain [M][K]
// ============================================================
__global__ __launch_bounds__(256) void convert_ctx_kernel()
{
    int idx = blockIdx.x * 256 + threadIdx.x;
    int mr = idx >> 9;
    int k  = (idx & 511) * 2;
    float2 v = *(const float2*)(g_ctx + (size_t)mr * HID + k);
    float2 g = *(const float2*)(g_gain + k);
    __half h0 = __float2half_rn(v.x * g.x);
    __half h1 = __float2half_rn(v.y * g.y);
    uint32_t hi = (uint32_t)__half_as_ushort(h0) | ((uint32_t)__half_as_ushort(h1) << 16);
    *(uint32_t*)((__half*)g_A_hi + (size_t)mr * HID + k) = hi;
}

// ============================================================
// Kernel 4: Wout [K][N] f32 -> g_B_hi [NPAD][K] fp16 (transpose)
// ============================================================
__global__ __launch_bounds__(256) void convert_wout_kernel(const float* __restrict__ W)
{
    __shared__ uint16_t s_hi[128][66];
    const int t = threadIdx.x;
    const int k0 = blockIdx.x * 64;
    const int n0 = blockIdx.y * 128;

    for (int it = 0; it < 32; it++) {
        int idx = it * 256 + t;        // 64k x 128n
        int k = idx >> 7, n = idx & 127;
        int gn = n0 + n;
        float v = (gn < VOCAB) ? __ldg(W + (size_t)(k0 + k) * VOCAB + gn) : 0.f;
        s_hi[n][k] = __half_as_ushort(__float2half_rn(v));
    }
    __syncthreads();

    for (int it = 0; it < 16; it++) {
        int u = it * 256 + t;          // 128 n-rows x 32 uint32
        int nn = u >> 5, ku = (u & 31) * 2;
        uint32_t hv = *(uint32_t*)&s_hi[nn][ku];
        size_t e = (size_t)(n0 + nn) * HID + k0 + ku;
        *(uint32_t*)((__half*)g_B_hi + e) = hv;
    }
}

// ============================================================
// Kernel 5: out = A @ B^T + bias via mma.sync fp16
// R8 config (fastest measured): CTA 128x128, 256 threads,
// 2 CTAs/SM, BK=64, 3-stage cp.async pipeline, one sync/chunk.
// ============================================================
#define BK 64
#define SROW 72                        /* fp16 per smem row (pad 8) */
#define ARR_B (128 * SROW * 2)         /* 18432 B per array */
#define STG_B (2 * ARR_B)              /* Ah | Bh = 36864 B */
#define NSTG 3
#define NCHUNK (HID / BK)              /* 16 */

__global__ __launch_bounds__(256, 2) void gemm_mma_kernel(
    const float* __restrict__ bias, float* __restrict__ C)
{
    extern __shared__ __align__(16) char sm[];
    const uint32_t sb = smem_u32(sm);
    const int t = threadIdx.x, lane = t & 31, wid = t >> 5;
    const int m0 = blockIdx.x * 128, n0 = blockIdx.y * 128;
    const int m0w = (wid & 3) * 32, n0w = (wid >> 2) * 64;

    float acc[2][8][4];
    #pragma unroll
    for (int i = 0; i < 2; i++)
        #pragma unroll
        for (int j = 0; j < 8; j++)
            #pragma unroll
            for (int q = 0; q < 4; q++) acc[i][j][q] = 0.f;

    const __half* srcA = g_A_hi + (size_t)m0 * HID;
    const __half* srcB = g_B_hi + (size_t)n0 * HID;

    auto issue = [&](int c) {
        uint32_t stg = sb + (uint32_t)(c % NSTG) * STG_B;
        int k0 = c * BK;
        #pragma unroll
        for (int a = 0; a < 2; a++) {
            uint32_t dbase = stg + a * ARR_B;
            const __half* gp = (a == 0 ? srcA : srcB) + k0;
            #pragma unroll
            for (int it = 0; it < 4; it++) {
                int idx = it * 256 + t;
                int row = idx >> 3, seg = idx & 7;
                uint32_t d = dbase + row * (SROW * 2) + seg * 16;
                CP_ASYNC16(d, gp + (size_t)row * HID + seg * 8);
            }
        }
        CP_COMMIT();
    };

    issue(0); issue(1);
    for (int c = 0; c < NCHUNK; c++) {
        if (c + 1 < NCHUNK) { CP_WAIT1(); } else { CP_WAIT0(); }
        __syncthreads();
        // stage (c+2)%3 was fully consumed at iteration c-1 (fenced above)
        if (c + 2 < NCHUNK) issue(c + 2);

        uint32_t stg = sb + (uint32_t)(c % NSTG) * STG_B;
        uint32_t pAh = stg, pBh = stg + ARR_B;

        #pragma unroll
        for (int ks = 0; ks < 4; ks++) {
            int kb = ks * 16;
            uint32_t acol = (uint32_t)(kb + ((lane >> 4) << 3)) * 2;

            uint32_t ah[2][4];
            #pragma unroll
            for (int mt = 0; mt < 2; mt++) {
                uint32_t ra = (uint32_t)(m0w + mt*16 + (lane & 15)) * (SROW*2) + acol;
                LDSM_X4(ah[mt], pAh + ra);
            }
            uint32_t bh[8][2];
            {
                int g = lane >> 3;
                int browoff = (g & 1) * 8 + (lane & 7);
                int bcoloff = (g >> 1) * 8;
                #pragma unroll
                for (int np = 0; np < 4; np++) {
                    uint32_t r4[4];
                    uint32_t rb = (uint32_t)(n0w + np*16 + browoff) * (SROW*2)
                                + (uint32_t)(kb + bcoloff) * 2;
                    LDSM_X4(r4, pBh + rb);
                    bh[2*np  ][0] = r4[0]; bh[2*np  ][1] = r4[2];
                    bh[2*np+1][0] = r4[1]; bh[2*np+1][1] = r4[3];
                }
            }
            #pragma unroll
            for (int mt = 0; mt < 2; mt++)
                #pragma unroll
                for (int nt = 0; nt < 8; nt++)
                    MMA16816(acc[mt][nt], ah[mt], bh[nt]);
        }
    }

    // ---- epilogue: + bias, store ----
    const bool full = (n0 + 128 <= VOCAB);
    #pragma unroll
    for (int mt = 0; mt < 2; mt++) {
        int r0 = m0 + m0w + mt*16 + (lane >> 2);
        #pragma unroll
        for (int nt = 0; nt < 8; nt++) {
            int cn = n0 + n0w + nt*8 + ((lane & 3) << 1);
            float* c0p = C + (size_t)r0 * VOCAB + cn;
            float* c1p = c0p + (size_t)8 * VOCAB;
            if (full) {
                float b0 = __ldg(bias + cn), b1 = __ldg(bias + cn + 1);
                float v0 = acc[mt][nt][0] + b0, v1 = acc[mt][nt][1] + b1;
                float v2 = acc[mt][nt][2] + b0, v3 = acc[mt][nt][3] + b1;
                if (!(((size_t)r0 * VOCAB + cn) & 1)) {
                    *(float2*)c0p = make_float2(v0, v1);
                } else { c0p[0] = v0; c0p[1] = v1; }
                if (!(((size_t)(r0+8) * VOCAB + cn) & 1)) {
                    *(float2*)c1p = make_float2(v2, v3);
                } else { c1p[0] = v2; c1p[1] = v3; }
            } else {
                if (cn < VOCAB) {
                    float b0 = __ldg(bias + cn);
                    c0p[0] = acc[mt][nt][0] + b0;
                    c1p[0] = acc[mt][nt][2] + b0;
                }
                if (cn + 1 < VOCAB) {
                    float b1 = __ldg(bias + cn + 1);
                    c0p[1] = acc[mt][nt][1] + b1;
                    c1p[1] = acc[mt][nt][3] + b1;
                }
            }
        }
    }
}

// ============================================================
extern "C" void kernel_launch(void* const* d_in, const int* in_sizes, int n_in,
                              void* d_out, int out_size)
{
    const float* x    = (const float*)d_in[0];
    const float* Wg   = (const float*)d_in[1];
    const float* bg   = (const float*)d_in[2];
    const float* We   = (const float*)d_in[3];
    const float* be   = (const float*)d_in[4];
    const float* Wo   = (const float*)d_in[5];
    const float* bo   = (const float*)d_in[6];
    const float* Wout = (const float*)d_in[7];
    const float* bout = (const float*)d_in[8];
    float* out = (float*)d_out;

    const int ctx_smem  = 16*DIN*4 + 16*256*4 + 16*8*4 + 16*32*4;   // 154112
    const int gemm_smem = NSTG * STG_B;                              // 110592
    cudaFuncSetAttribute(fused_ctx_kernel, cudaFuncAttributeMaxDynamicSharedMemorySize, ctx_smem);
    cudaFuncSetAttribute(gemm_mma_kernel,  cudaFuncAttributeMaxDynamicSharedMemorySize, gemm_smem);

    convert_wout_kernel<<<dim3(16, NT128), 256>>>(Wout);
    fused_ctx_kernel<<<BATCH/16, 256, ctx_smem>>>(x, Wg, bg, We, be, Wo, bo);
    topk_gain_kernel<<<1, 256>>>();
    convert_ctx_kernel<<<(BATCH*HID/2)/256, 256>>>();
    gemm_mma_kernel<<<dim3(MT128, NT128), 256, gemm_smem>>>(bout, out);
}

// round 13
// speedup vs baseline: 1.2315x; 1.0033x over previous
#include <cuda_runtime.h>
#include <cuda_fp16.h>
#include <math.h>
#include <stdint.h>

#define BATCH 2048
#define FEAT  2048
#define HARM  32
#define DIN   (FEAT + 2*HARM)   /* 2112 */
#define NEXP  8
#define EDIM  32
#define HID   1024
#define VOCAB 50257
#define NPAD  50432
#define NT128 394
#define MT128 16

// ---------------- device scratch (no allocations allowed) ----------------
__device__ __align__(16) float  g_ctx[BATCH * HID];          // 8 MB
__device__ __align__(16) float  g_gain[HID];
__device__ __align__(16) __half g_A_hi[BATCH * HID];         // [2048][1024]
__device__ __align__(16) __half g_B_hi[(size_t)NPAD * HID];  // [NPAD][1024] (Wout^T)

__device__ __forceinline__ uint32_t smem_u32(const void* p) {
    uint32_t a;
    asm("{ .reg .u64 t; cvta.to.shared.u64 t, %1; cvt.u32.u64 %0, t; }" : "=r"(a) : "l"(p));
    return a;
}

#define LDSM_X4(r, a) asm volatile( \
    "ldmatrix.sync.aligned.m8n8.x4.shared.b16 {%0,%1,%2,%3}, [%4];" \
    : "=r"((r)[0]),"=r"((r)[1]),"=r"((r)[2]),"=r"((r)[3]) : "r"(a))
#define MMA16816(c, a, b) asm volatile( \
    "mma.sync.aligned.m16n8k16.row.col.f32.f16.f16.f32 " \
    "{%0,%1,%2,%3},{%4,%5,%6,%7},{%8,%9},{%0,%1,%2,%3};" \
    : "+f"((c)[0]),"+f"((c)[1]),"+f"((c)[2]),"+f"((c)[3]) \
    : "r"((a)[0]),"r"((a)[1]),"r"((a)[2]),"r"((a)[3]), "r"((b)[0]),"r"((b)[1]))
#define CP_ASYNC16(d, s) asm volatile( \
    "cp.async.cg.shared.global [%0], [%1], 16;" :: "r"(d), "l"(s) : "memory")
#define CP_COMMIT() asm volatile("cp.async.commit_group;" ::: "memory")
#define CP_WAIT1()  asm volatile("cp.async.wait_group 1;" ::: "memory")
#define CP_WAIT0()  asm volatile("cp.async.wait_group 0;" ::: "memory")

// ============================================================
// Kernel 1: fused ctx — 8 samples per block, 256 blocks.
// 77KB smem -> 2 blocks/SM -> 4 warps/SMSP (latency hiding for
// the LDS/LDG-interleaved FFMA stream; 1 block/SM was issue-starved).
// ============================================================
#define CSAMP 8
__global__ __launch_bounds__(256) void fused_ctx_kernel(
    const float* __restrict__ x,
    const float* __restrict__ Wg, const float* __restrict__ bg,
    const float* __restrict__ We, const float* __restrict__ be,
    const float* __restrict__ Wo, const float* __restrict__ bo)
{
    extern __shared__ __align__(16) char sm[];
    float* enh    = (float*)sm;                              // [8][2112]
    float* eo_s   = (float*)(sm + CSAMP*DIN*4);              // [8][256]
    float* logits = (float*)(sm + CSAMP*DIN*4 + CSAMP*256*4);// [8][8]
    float* mixed  = logits + CSAMP*8;                        // [8][32]

    const int t = threadIdx.x;
    const int wid = t >> 5, lane = t & 31;
    const int b0 = blockIdx.x * CSAMP;

    // phase 1: each warp handles 1 sample: load row, mean, phasor
    {
        int s = wid;
        const float4* xr = (const float4*)(x + (size_t)(b0 + s) * FEAT);
        float* er = enh + s * DIN;
        float sum = 0.f;
        #pragma unroll 4
        for (int i = lane; i < FEAT/4; i += 32) {
            float4 v = xr[i];
            *(float4*)(er + 4*i) = v;
            sum += (v.x + v.y) + (v.z + v.w);
        }
        #pragma unroll
        for (int o = 16; o > 0; o >>= 1) sum += __shfl_xor_sync(0xffffffffu, sum, o);
        float mean = sum * (1.0f / FEAT);
        float base = 43.98229715025711f * mean;   // 2*pi*7
        float ph = base * (float)(lane + 1);
        er[FEAT + lane]        = cosf(ph);
        er[FEAT + HARM + lane] = sinf(ph);
    }
    __syncthreads();

    // phase 2a: 256 expert outputs, exactly one per thread
    {
        const int e = t >> 5, h = t & 31;
        const float* wp = We + (size_t)e * DIN * EDIM + h;
        float acc[CSAMP];
        #pragma unroll
        for (int s = 0; s < CSAMP; s++) acc[s] = 0.f;
        for (int d = 0; d < DIN; d += 4) {
            float w0 = wp[(size_t)(d+0) * EDIM];
            float w1 = wp[(size_t)(d+1) * EDIM];
            float w2 = wp[(size_t)(d+2) * EDIM];
            float w3 = wp[(size_t)(d+3) * EDIM];
            #pragma unroll
            for (int s = 0; s < CSAMP; s++) {
                float4 ev = *(const float4*)(enh + s*DIN + d);
                float a = acc[s];
                a = fmaf(ev.x, w0, a); a = fmaf(ev.y, w1, a);
                a = fmaf(ev.z, w2, a); a = fmaf(ev.w, w3, a);
                acc[s] = a;
            }
        }
        #pragma unroll
        for (int s = 0; s < CSAMP; s++) eo_s[s*256 + t] = acc[s] + be[t];
    }

    // phase 2b: 8 gate logits, one per warp, shuffle-reduced over DIN
    {
        const int e = wid;
        float acc[CSAMP];
        #pragma unroll
        for (int s = 0; s < CSAMP; s++) acc[s] = 0.f;
        for (int d = lane; d < DIN; d += 32) {
            float w = Wg[(size_t)d * NEXP + e];
            #pragma unroll
            for (int s = 0; s < CSAMP; s++)
                acc[s] = fmaf(enh[s*DIN + d], w, acc[s]);
        }
        #pragma unroll
        for (int s = 0; s < CSAMP; s++) {
            float v = acc[s];
            #pragma unroll
            for (int o = 16; o > 0; o >>= 1) v += __shfl_xor_sync(0xffffffffu, v, o);
            if (lane == 0) logits[s*8 + e] = v + bg[e];
        }
    }
    __syncthreads();

    // phase 3: softmax per sample
    if (t < CSAMP) {
        float* lg = logits + t*8;
        float mx = lg[0];
        #pragma unroll
        for (int e = 1; e < 8; e++) mx = fmaxf(mx, lg[e]);
        float ss = 0.f;
        #pragma unroll
        for (int e = 0; e < 8; e++) { float ex = expf(lg[e] - mx); lg[e] = ex; ss += ex; }
        float inv = 1.0f / ss;
        #pragma unroll
        for (int e = 0; e < 8; e++) lg[e] *= inv;
    }
    __syncthreads();

    // phase 4: mixed[s][h] — 8*32 = 256 = one per thread
    {
        int s = t >> 5, h = t & 31;
        float m = 0.f;
        #pragma unroll
        for (int e = 0; e < 8; e++) m = fmaf(logits[s*8 + e], eo_s[s*256 + e*32 + h], m);
        mixed[t] = m;
    }
    __syncthreads();

    // phase 5: ctx = tanh(mixed @ Wo + bo)
    for (int it = 0; it < 4; it++) {
        int o = t + it * 256;
        float acc[CSAMP];
        float bb = bo[o];
        #pragma unroll
        for (int s = 0; s < CSAMP; s++) acc[s] = bb;
        for (int k = 0; k < EDIM; k++) {
            float w = Wo[(size_t)k * HID + o];
            #pragma unroll
            for (int s = 0; s < CSAMP; s++) acc[s] = fmaf(mixed[s*32 + k], w, acc[s]);
        }
        #pragma unroll
        for (int s = 0; s < CSAMP; s++)
            g_ctx[(size_t)(b0 + s) * HID + o] = tanhf(acc[s]);
    }
}

// ============================================================
// Kernel 2: top-20 of ctx[0,:] -> gain (spiking scan collapses)
// ============================================================
__global__ __launch_bounds__(256) void topk_gain_kernel()
{
    __shared__ float vals[HID];
    __shared__ float rv[256];
    __shared__ int   ri[256];
    const int t = threadIdx.x;
    for (int i = t; i < HID; i += 256) { vals[i] = g_ctx[i]; g_gain[i] = 1.0f; }
    __syncthreads();
    for (int it = 0; it < 20; it++) {
        float best = -1e30f; int bi = 0;
        for (int i = t; i < HID; i += 256)
            if (vals[i] > best) { best = vals[i]; bi = i; }
        rv[t] = best; ri[t] = bi;
        __syncthreads();
        for (int s = 128; s > 0; s >>= 1) {
            if (t < s && rv[t + s] > rv[t]) { rv[t] = rv[t + s]; ri[t] = ri[t + s]; }
            __syncthreads();
        }
        if (t == 0) { g_gain[ri[0]] = 2.0f; vals[ri[0]] = -1e30f; }
        __syncthreads();
    }
}

// ============================================================
// Kernel 3: convert ctx*gain -> fp16, plain [M][K]
// ============================================================
__global__ __launch_bounds__(256) void convert_ctx_kernel()
{
    int idx = blockIdx.x * 256 + threadIdx.x;
    int mr = idx >> 9;
    int k  = (idx & 511) * 2;
    float2 v = *(const float2*)(g_ctx + (size_t)mr * HID + k);
    float2 g = *(const float2*)(g_gain + k);
    __half h0 = __float2half_rn(v.x * g.x);
    __half h1 = __float2half_rn(v.y * g.y);
    uint32_t hi = (uint32_t)__half_as_ushort(h0) | ((uint32_t)__half_as_ushort(h1) << 16);
    *(uint32_t*)((__half*)g_A_hi + (size_t)mr * HID + k) = hi;
}

// ============================================================
// Kernel 4: Wout [K][N] f32 -> g_B_hi [NPAD][K] fp16 (transpose)
// ============================================================
__global__ __launch_bounds__(256) void convert_wout_kernel(const float* __restrict__ W)
{
    __shared__ uint16_t s_hi[128][66];
    const int t = threadIdx.x;
    const int k0 = blockIdx.x * 64;
    const int n0 = blockIdx.y * 128;

    for (int it = 0; it < 32; it++) {
        int idx = it * 256 + t;        // 64k x 128n
        int k = idx >> 7, n = idx & 127;
        int gn = n0 + n;
        float v = (gn < VOCAB) ? __ldg(W + (size_t)(k0 + k) * VOCAB + gn) : 0.f;
        s_hi[n][k] = __half_as_ushort(__float2half_rn(v));
    }
    __syncthreads();

    for (int it = 0; it < 16; it++) {
        int u = it * 256 + t;          // 128 n-rows x 32 uint32
        int nn = u >> 5, ku = (u & 31) * 2;
        uint32_t hv = *(uint32_t*)&s_hi[nn][ku];
        size_t e = (size_t)(n0 + nn) * HID + k0 + ku;
        *(uint32_t*)((__half*)g_B_hi + e) = hv;
    }
}

// ============================================================
// Kernel 5: out = A @ B^T + bias via mma.sync fp16
// R8 config (fastest measured): CTA 128x128, 256 threads,
// 2 CTAs/SM, BK=64, 3-stage cp.async pipeline, one sync/chunk.
// ============================================================
#define BK 64
#define SROW 72                        /* fp16 per smem row (pad 8) */
#define ARR_B (128 * SROW * 2)         /* 18432 B per array */
#define STG_B (2 * ARR_B)              /* Ah | Bh = 36864 B */
#define NSTG 3
#define NCHUNK (HID / BK)              /* 16 */

__global__ __launch_bounds__(256, 2) void gemm_mma_kernel(
    const float* __restrict__ bias, float* __restrict__ C)
{
    extern __shared__ __align__(16) char sm[];
    const uint32_t sb = smem_u32(sm);
    const int t = threadIdx.x, lane = t & 31, wid = t >> 5;
    const int m0 = blockIdx.x * 128, n0 = blockIdx.y * 128;
    const int m0w = (wid & 3) * 32, n0w = (wid >> 2) * 64;

    float acc[2][8][4];
    #pragma unroll
    for (int i = 0; i < 2; i++)
        #pragma unroll
        for (int j = 0; j < 8; j++)
            #pragma unroll
            for (int q = 0; q < 4; q++) acc[i][j][q] = 0.f;

    const __half* srcA = g_A_hi + (size_t)m0 * HID;
    const __half* srcB = g_B_hi + (size_t)n0 * HID;

    auto issue = [&](int c) {
        uint32_t stg = sb + (uint32_t)(c % NSTG) * STG_B;
        int k0 = c * BK;
        #pragma unroll
        for (int a = 0; a < 2; a++) {
            uint32_t dbase = stg + a * ARR_B;
            const __half* gp = (a == 0 ? srcA : srcB) + k0;
            #pragma unroll
            for (int it = 0; it < 4; it++) {
                int idx = it * 256 + t;
                int row = idx >> 3, seg = idx & 7;
                uint32_t d = dbase + row * (SROW * 2) + seg * 16;
                CP_ASYNC16(d, gp + (size_t)row * HID + seg * 8);
            }
        }
        CP_COMMIT();
    };

    issue(0); issue(1);
    for (int c = 0; c < NCHUNK; c++) {
        if (c + 1 < NCHUNK) { CP_WAIT1(); } else { CP_WAIT0(); }
        __syncthreads();
        // stage (c+2)%3 was fully consumed at iteration c-1 (fenced above)
        if (c + 2 < NCHUNK) issue(c + 2);

        uint32_t stg = sb + (uint32_t)(c % NSTG) * STG_B;
        uint32_t pAh = stg, pBh = stg + ARR_B;

        #pragma unroll
        for (int ks = 0; ks < 4; ks++) {
            int kb = ks * 16;
            uint32_t acol = (uint32_t)(kb + ((lane >> 4) << 3)) * 2;

            uint32_t ah[2][4];
            #pragma unroll
            for (int mt = 0; mt < 2; mt++) {
                uint32_t ra = (uint32_t)(m0w + mt*16 + (lane & 15)) * (SROW*2) + acol;
                LDSM_X4(ah[mt], pAh + ra);
            }
            uint32_t bh[8][2];
            {
                int g = lane >> 3;
                int browoff = (g & 1) * 8 + (lane & 7);
                int bcoloff = (g >> 1) * 8;
                #pragma unroll
                for (int np = 0; np < 4; np++) {
                    uint32_t r4[4];
                    uint32_t rb = (uint32_t)(n0w + np*16 + browoff) * (SROW*2)
                                + (uint32_t)(kb + bcoloff) * 2;
                    LDSM_X4(r4, pBh + rb);
                    bh[2*np  ][0] = r4[0]; bh[2*np  ][1] = r4[2];
                    bh[2*np+1][0] = r4[1]; bh[2*np+1][1] = r4[3];
                }
            }
            #pragma unroll
            for (int mt = 0; mt < 2; mt++)
                #pragma unroll
                for (int nt = 0; nt < 8; nt++)
                    MMA16816(acc[mt][nt], ah[mt], bh[nt]);
        }
    }

    // ---- epilogue: + bias, store ----
    const bool full = (n0 + 128 <= VOCAB);
    #pragma unroll
    for (int mt = 0; mt < 2; mt++) {
        int r0 = m0 + m0w + mt*16 + (lane >> 2);
        #pragma unroll
        for (int nt = 0; nt < 8; nt++) {
            int cn = n0 + n0w + nt*8 + ((lane & 3) << 1);
            float* c0p = C + (size_t)r0 * VOCAB + cn;
            float* c1p = c0p + (size_t)8 * VOCAB;
            if (full) {
                float b0 = __ldg(bias + cn), b1 = __ldg(bias + cn + 1);
                float v0 = acc[mt][nt][0] + b0, v1 = acc[mt][nt][1] + b1;
                float v2 = acc[mt][nt][2] + b0, v3 = acc[mt][nt][3] + b1;
                if (!(((size_t)r0 * VOCAB + cn) & 1)) {
                    *(float2*)c0p = make_float2(v0, v1);
                } else { c0p[0] = v0; c0p[1] = v1; }
                if (!(((size_t)(r0+8) * VOCAB + cn) & 1)) {
                    *(float2*)c1p = make_float2(v2, v3);
                } else { c1p[0] = v2; c1p[1] = v3; }
            } else {
                if (cn < VOCAB) {
                    float b0 = __ldg(bias + cn);
                    c0p[0] = acc[mt][nt][0] + b0;
                    c1p[0] = acc[mt][nt][2] + b0;
                }
                if (cn + 1 < VOCAB) {
                    float b1 = __ldg(bias + cn + 1);
                    c0p[1] = acc[mt][nt][1] + b1;
                    c1p[1] = acc[mt][nt][3] + b1;
                }
            }
        }
    }
}

// ============================================================
extern "C" void kernel_launch(void* const* d_in, const int* in_sizes, int n_in,
                              void* d_out, int out_size)
{
    const float* x    = (const float*)d_in[0];
    const float* Wg   = (const float*)d_in[1];
    const float* bg   = (const float*)d_in[2];
    const float* We   = (const float*)d_in[3];
    const float* be   = (const float*)d_in[4];
    const float* Wo   = (const float*)d_in[5];
    const float* bo   = (const float*)d_in[6];
    const float* Wout = (const float*)d_in[7];
    const float* bout = (const float*)d_in[8];
    float* out = (float*)d_out;

    const int ctx_smem  = CSAMP*DIN*4 + CSAMP*256*4 + CSAMP*8*4 + CSAMP*32*4;  // 77056
    const int gemm_smem = NSTG * STG_B;                                         // 110592
    cudaFuncSetAttribute(fused_ctx_kernel, cudaFuncAttributeMaxDynamicSharedMemorySize, ctx_smem);
    cudaFuncSetAttribute(gemm_mma_kernel,  cudaFuncAttributeMaxDynamicSharedMemorySize, gemm_smem);

    convert_wout_kernel<<<dim3(16, NT128), 256>>>(Wout);
    fused_ctx_kernel<<<BATCH/CSAMP, 256, ctx_smem>>>(x, Wg, bg, We, be, Wo, bo);
    topk_gain_kernel<<<1, 256>>>();
    convert_ctx_kernel<<<(BATCH*HID/2)/256, 256>>>();
    gemm_mma_kernel<<<dim3(MT128, NT128), 256, gemm_smem>>>(bout, out);
}

// round 14
// speedup vs baseline: 1.3899x; 1.1286x over previous
#include <cuda_runtime.h>
#include <cuda_fp16.h>
#include <math.h>
#include <stdint.h>

#define BATCH 2048
#define FEAT  2048
#define HARM  32
#define DIN   (FEAT + 2*HARM)   /* 2112 */
#define NEXP  8
#define EDIM  32
#define HID   1024
#define VOCAB 50257
#define NPAD  50432
#define NT128 394
#define MT128 16

// ---------------- device scratch (no allocations allowed) ----------------
__device__ __align__(16) float  g_ctx[BATCH * HID];          // 8 MB
__device__ __align__(16) float  g_gain[HID];
__device__ __align__(16) __half g_A_hi[BATCH * HID];         // [2048][1024]
__device__ __align__(16) __half g_B_hi[(size_t)NPAD * HID];  // [NPAD][1024] (Wout^T)

__device__ __forceinline__ uint32_t smem_u32(const void* p) {
    uint32_t a;
    asm("{ .reg .u64 t; cvta.to.shared.u64 t, %1; cvt.u32.u64 %0, t; }" : "=r"(a) : "l"(p));
    return a;
}

#define LDSM_X4(r, a) asm volatile( \
    "ldmatrix.sync.aligned.m8n8.x4.shared.b16 {%0,%1,%2,%3}, [%4];" \
    : "=r"((r)[0]),"=r"((r)[1]),"=r"((r)[2]),"=r"((r)[3]) : "r"(a))
#define MMA16816(c, a, b) asm volatile( \
    "mma.sync.aligned.m16n8k16.row.col.f32.f16.f16.f32 " \
    "{%0,%1,%2,%3},{%4,%5,%6,%7},{%8,%9},{%0,%1,%2,%3};" \
    : "+f"((c)[0]),"+f"((c)[1]),"+f"((c)[2]),"+f"((c)[3]) \
    : "r"((a)[0]),"r"((a)[1]),"r"((a)[2]),"r"((a)[3]), "r"((b)[0]),"r"((b)[1]))
#define CP_ASYNC16(d, s) asm volatile( \
    "cp.async.cg.shared.global [%0], [%1], 16;" :: "r"(d), "l"(s) : "memory")
#define CP_COMMIT() asm volatile("cp.async.commit_group;" ::: "memory")
#define CP_WAIT1()  asm volatile("cp.async.wait_group 1;" ::: "memory")
#define CP_WAIT0()  asm volatile("cp.async.wait_group 0;" ::: "memory")

// ============================================================
// Kernel 1: fused ctx — 8 samples per block, 512 threads, split-K.
// Each dot product is split over 2 threads (half of DIN each):
// halves the serial load->FMA chain that bound previous versions.
// ============================================================
#define CSAMP 8
#define DHALF (DIN / 2)          /* 1056 */

// smem offsets (bytes)
#define OFF_ENH    0
#define OFF_EO     (CSAMP*DIN*4)                 /* 67584 */
#define OFF_PART   (OFF_EO + CSAMP*256*4)        /* 75776 */
#define OFF_LOGIT  (OFF_PART + CSAMP*256*4)      /* 83968 */
#define OFF_MIXED  (OFF_LOGIT + CSAMP*8*4)       /* 84224 */
#define OFF_PSUM   (OFF_MIXED + CSAMP*32*4)      /* 85248 */
#define OFF_GLOG   (OFF_PSUM + 16*4)             /* 85312 */
#define CTX_SMEM   (OFF_GLOG + 128*4)            /* 85824 */

__global__ __launch_bounds__(512) void fused_ctx_kernel(
    const float* __restrict__ x,
    const float* __restrict__ Wg, const float* __restrict__ bg,
    const float* __restrict__ We, const float* __restrict__ be,
    const float* __restrict__ Wo, const float* __restrict__ bo)
{
    extern __shared__ __align__(16) char sm[];
    float* enh    = (float*)(sm + OFF_ENH);     // [8][2112]
    float* eo_s   = (float*)(sm + OFF_EO);      // [8][256]
    float* part   = (float*)(sm + OFF_PART);    // [8][256] (kidx=1 partials)
    float* logits = (float*)(sm + OFF_LOGIT);   // [8][8]
    float* mixed  = (float*)(sm + OFF_MIXED);   // [8][32]
    float* psum   = (float*)(sm + OFF_PSUM);    // [16]
    float* glog   = (float*)(sm + OFF_GLOG);    // [2][8][8] (half,s,e)

    const int t = threadIdx.x;
    const int wid = t >> 5, lane = t & 31;
    const int b0 = blockIdx.x * CSAMP;

    // phase 1: 16 warps, warp = (half, sample); load half-row + partial sum
    {
        int s = wid & 7, half = wid >> 3;
        const float4* xr = (const float4*)(x + (size_t)(b0 + s) * FEAT + half * (FEAT/2));
        float* er = enh + s * DIN + half * (FEAT/2);
        float sum = 0.f;
        #pragma unroll
        for (int i = lane; i < FEAT/8; i += 32) {   // 256 float4 per half
            float4 v = xr[i];
            *(float4*)(er + 4*i) = v;
            sum += (v.x + v.y) + (v.z + v.w);
        }
        #pragma unroll
        for (int o = 16; o > 0; o >>= 1) sum += __shfl_xor_sync(0xffffffffu, sum, o);
        if (lane == 0) psum[wid] = sum;
    }
    __syncthreads();
    // phasor: warps 0..7, one per sample
    if (wid < 8) {
        float mean = (psum[wid] + psum[wid + 8]) * (1.0f / FEAT);
        float base = 43.98229715025711f * mean;   // 2*pi*7
        float ph = base * (float)(lane + 1);
        float* er = enh + wid * DIN;
        er[FEAT + lane]        = cosf(ph);
        er[FEAT + HARM + lane] = sinf(ph);
    }
    __syncthreads();

    // phase 2a: 256 expert outputs x 2 K-halves = 512 threads
    float acc[CSAMP];
    {
        const int kidx = t >> 8;           // K-half
        const int tt = t & 255;            // output index
        const int e = tt >> 5, h = tt & 31;
        const float* wp = We + (size_t)e * DIN * EDIM + h;
        const int d0 = kidx * DHALF;
        #pragma unroll
        for (int s = 0; s < CSAMP; s++) acc[s] = 0.f;
        for (int d = d0; d < d0 + DHALF; d += 4) {
            float w0 = wp[(size_t)(d+0) * EDIM];
            float w1 = wp[(size_t)(d+1) * EDIM];
            float w2 = wp[(size_t)(d+2) * EDIM];
            float w3 = wp[(size_t)(d+3) * EDIM];
            #pragma unroll
            for (int s = 0; s < CSAMP; s++) {
                float4 ev = *(const float4*)(enh + s*DIN + d);
                float a = acc[s];
                a = fmaf(ev.x, w0, a); a = fmaf(ev.y, w1, a);
                a = fmaf(ev.z, w2, a); a = fmaf(ev.w, w3, a);
                acc[s] = a;
            }
        }
        if (kidx == 1) {
            #pragma unroll
            for (int s = 0; s < CSAMP; s++) part[s*256 + tt] = acc[s];
        }
    }

    // phase 2b: 8 gates x 2 K-halves = 16 warps, shuffle-reduced
    {
        const int e = wid & 7, half = wid >> 3;
        const int d0 = half * DHALF;
        float ag[CSAMP];
        #pragma unroll
        for (int s = 0; s < CSAMP; s++) ag[s] = 0.f;
        for (int d = d0 + lane; d < d0 + DHALF; d += 32) {
            float w = Wg[(size_t)d * NEXP + e];
            #pragma unroll
            for (int s = 0; s < CSAMP; s++)
                ag[s] = fmaf(enh[s*DIN + d], w, ag[s]);
        }
        #pragma unroll
        for (int s = 0; s < CSAMP; s++) {
            float v = ag[s];
            #pragma unroll
            for (int o = 16; o > 0; o >>= 1) v += __shfl_xor_sync(0xffffffffu, v, o);
            if (lane == 0) glog[half*64 + s*8 + e] = v;
        }
    }
    __syncthreads();

    // combine expert partials (threads 0..255 still hold kidx=0 acc in regs)
    if (t < 256) {
        #pragma unroll
        for (int s = 0; s < CSAMP; s++)
            eo_s[s*256 + t] = acc[s] + part[s*256 + t] + be[t];
    }
    // combine gate partials
    if (t < 64) {
        int s = t >> 3, e = t & 7;
        logits[s*8 + e] = glog[s*8 + e] + glog[64 + s*8 + e] + bg[e];
    }
    __syncthreads();

    // phase 3: softmax per sample
    if (t < CSAMP) {
        float* lg = logits + t*8;
        float mx = lg[0];
        #pragma unroll
        for (int e = 1; e < 8; e++) mx = fmaxf(mx, lg[e]);
        float ss = 0.f;
        #pragma unroll
        for (int e = 0; e < 8; e++) { float ex = expf(lg[e] - mx); lg[e] = ex; ss += ex; }
        float inv = 1.0f / ss;
        #pragma unroll
        for (int e = 0; e < 8; e++) lg[e] *= inv;
    }
    __syncthreads();

    // phase 4: mixed[s][h]
    if (t < 256) {
        int s = t >> 5, h = t & 31;
        float m = 0.f;
        #pragma unroll
        for (int e = 0; e < 8; e++) m = fmaf(logits[s*8 + e], eo_s[s*256 + e*32 + h], m);
        mixed[t] = m;
    }
    __syncthreads();

    // phase 5: ctx = tanh(mixed @ Wo + bo): 1024 outputs / 512 threads
    #pragma unroll
    for (int it = 0; it < 2; it++) {
        int o = t + it * 512;
        float a5[CSAMP];
        float bb = bo[o];
        #pragma unroll
        for (int s = 0; s < CSAMP; s++) a5[s] = bb;
        for (int k = 0; k < EDIM; k++) {
            float w = Wo[(size_t)k * HID + o];
            #pragma unroll
            for (int s = 0; s < CSAMP; s++) a5[s] = fmaf(mixed[s*32 + k], w, a5[s]);
        }
        #pragma unroll
        for (int s = 0; s < CSAMP; s++)
            g_ctx[(size_t)(b0 + s) * HID + o] = tanhf(a5[s]);
    }
}

// ============================================================
// Kernel 2: top-20 of ctx[0,:] -> gain (spiking scan collapses)
// ============================================================
__global__ __launch_bounds__(256) void topk_gain_kernel()
{
    __shared__ float vals[HID];
    __shared__ float rv[256];
    __shared__ int   ri[256];
    const int t = threadIdx.x;
    for (int i = t; i < HID; i += 256) { vals[i] = g_ctx[i]; g_gain[i] = 1.0f; }
    __syncthreads();
    for (int it = 0; it < 20; it++) {
        float best = -1e30f; int bi = 0;
        for (int i = t; i < HID; i += 256)
            if (vals[i] > best) { best = vals[i]; bi = i; }
        rv[t] = best; ri[t] = bi;
        __syncthreads();
        for (int s = 128; s > 0; s >>= 1) {
            if (t < s && rv[t + s] > rv[t]) { rv[t] = rv[t + s]; ri[t] = ri[t + s]; }
            __syncthreads();
        }
        if (t == 0) { g_gain[ri[0]] = 2.0f; vals[ri[0]] = -1e30f; }
        __syncthreads();
    }
}

// ============================================================
// Kernel 3: convert ctx*gain -> fp16, plain [M][K]
// ============================================================
__global__ __launch_bounds__(256) void convert_ctx_kernel()
{
    int idx = blockIdx.x * 256 + threadIdx.x;
    int mr = idx >> 9;
    int k  = (idx & 511) * 2;
    float2 v = *(const float2*)(g_ctx + (size_t)mr * HID + k);
    float2 g = *(const float2*)(g_gain + k);
    __half h0 = __float2half_rn(v.x * g.x);
    __half h1 = __float2half_rn(v.y * g.y);
    uint32_t hi = (uint32_t)__half_as_ushort(h0) | ((uint32_t)__half_as_ushort(h1) << 16);
    *(uint32_t*)((__half*)g_A_hi + (size_t)mr * HID + k) = hi;
}

// ============================================================
// Kernel 4: Wout [K][N] f32 -> g_B_hi [NPAD][K] fp16 (transpose)
// ============================================================
__global__ __launch_bounds__(256) void convert_wout_kernel(const float* __restrict__ W)
{
    __shared__ uint16_t s_hi[128][66];
    const int t = threadIdx.x;
    const int k0 = blockIdx.x * 64;
    const int n0 = blockIdx.y * 128;

    for (int it = 0; it < 32; it++) {
        int idx = it * 256 + t;        // 64k x 128n
        int k = idx >> 7, n = idx & 127;
        int gn = n0 + n;
        float v = (gn < VOCAB) ? __ldg(W + (size_t)(k0 + k) * VOCAB + gn) : 0.f;
        s_hi[n][k] = __half_as_ushort(__float2half_rn(v));
    }
    __syncthreads();

    for (int it = 0; it < 16; it++) {
        int u = it * 256 + t;          // 128 n-rows x 32 uint32
        int nn = u >> 5, ku = (u & 31) * 2;
        uint32_t hv = *(uint32_t*)&s_hi[nn][ku];
        size_t e = (size_t)(n0 + nn) * HID + k0 + ku;
        *(uint32_t*)((__half*)g_B_hi + e) = hv;
    }
}

// ============================================================
// Kernel 5: out = A @ B^T + bias via mma.sync fp16
// CTA 128x128, 256 threads, 2 CTAs/SM, BK=64, 3-stage cp.async
// pipeline, one sync/chunk + register double-buffered fragments.
// ============================================================
#define BK 64
#define SROW 72                        /* fp16 per smem row (pad 8) */
#define ARR_B (128 * SROW * 2)         /* 18432 B per array */
#define STG_B (2 * ARR_B)              /* Ah | Bh = 36864 B */
#define NSTG 3
#define NCHUNK (HID / BK)              /* 16 */

__global__ __launch_bounds__(256, 2) void gemm_mma_kernel(
    const float* __restrict__ bias, float* __restrict__ C)
{
    extern __shared__ __align__(16) char sm[];
    const uint32_t sb = smem_u32(sm);
    const int t = threadIdx.x, lane = t & 31, wid = t >> 5;
    const int m0 = blockIdx.x * 128, n0 = blockIdx.y * 128;
    const int m0w = (wid & 3) * 32, n0w = (wid >> 2) * 64;

    float acc[2][8][4];
    #pragma unroll
    for (int i = 0; i < 2; i++)
        #pragma unroll
        for (int j = 0; j < 8; j++)
            #pragma unroll
            for (int q = 0; q < 4; q++) acc[i][j][q] = 0.f;

    const __half* srcA = g_A_hi + (size_t)m0 * HID;
    const __half* srcB = g_B_hi + (size_t)n0 * HID;

    auto issue = [&](int c) {
        uint32_t stg = sb + (uint32_t)(c % NSTG) * STG_B;
        int k0 = c * BK;
        #pragma unroll
        for (int a = 0; a < 2; a++) {
            uint32_t dbase = stg + a * ARR_B;
            const __half* gp = (a == 0 ? srcA : srcB) + k0;
            #pragma unroll
            for (int it = 0; it < 4; it++) {
                int idx = it * 256 + t;
                int row = idx >> 3, seg = idx & 7;
                uint32_t d = dbase + row * (SROW * 2) + seg * 16;
                CP_ASYNC16(d, gp + (size_t)row * HID + seg * 8);
            }
        }
        CP_COMMIT();
    };

    // fragment ping-pong buffers
    uint32_t ah[2][2][4], bh[2][8][2];
    const int aRowOff = (lane & 15) * (SROW*2);
    const int aColSel = ((lane >> 4) << 3) * 2;
    const int gsel = lane >> 3;
    const int browoff = ((gsel & 1) * 8 + (lane & 7)) * (SROW*2);
    const int bcoloff = ((gsel >> 1) * 8) * 2;

    issue(0); issue(1);
    for (int c = 0; c < NCHUNK; c++) {
        if (c + 1 < NCHUNK) { CP_WAIT1(); } else { CP_WAIT0(); }
        __syncthreads();
        if (c + 2 < NCHUNK) issue(c + 2);

        uint32_t stg = sb + (uint32_t)(c % NSTG) * STG_B;
        uint32_t pAh = stg, pBh = stg + ARR_B;

        // preload ks=0 fragments
        {
            uint32_t abase = pAh + aRowOff + aColSel;
            LDSM_X4(ah[0][0], abase + (uint32_t)(m0w) * (SROW*2));
            LDSM_X4(ah[0][1], abase + (uint32_t)(m0w + 16) * (SROW*2));
            uint32_t bbase = pBh + browoff + bcoloff;
            #pragma unroll
            for (int np = 0; np < 4; np++) {
                uint32_t r4[4];
                LDSM_X4(r4, bbase + (uint32_t)(n0w + np*16) * (SROW*2));
                bh[0][2*np  ][0] = r4[0]; bh[0][2*np  ][1] = r4[2];
                bh[0][2*np+1][0] = r4[1]; bh[0][2*np+1][1] = r4[3];
            }
        }

        #pragma unroll
        for (int ks = 0; ks < 4; ks++) {
            const int cur = ks & 1, nxt = cur ^ 1;
            if (ks < 3) {
                int kb2 = (ks + 1) * 16 * 2;
                uint32_t abase = pAh + aRowOff + aColSel + kb2;
                LDSM_X4(ah[nxt][0], abase + (uint32_t)(m0w) * (SROW*2));
                LDSM_X4(ah[nxt][1], abase + (uint32_t)(m0w + 16) * (SROW*2));
                uint32_t bbase = pBh + browoff + bcoloff + kb2;
                #pragma unroll
                for (int np = 0; np < 4; np++) {
                    uint32_t r4[4];
                    LDSM_X4(r4, bbase + (uint32_t)(n0w + np*16) * (SROW*2));
                    bh[nxt][2*np  ][0] = r4[0]; bh[nxt][2*np  ][1] = r4[2];
                    bh[nxt][2*np+1][0] = r4[1]; bh[nxt][2*np+1][1] = r4[3];
                }
            }
            #pragma unroll
            for (int mt = 0; mt < 2; mt++)
                #pragma unroll
                for (int nt = 0; nt < 8; nt++)
                    MMA16816(acc[mt][nt], ah[cur][mt], bh[cur][nt]);
        }
    }

    // ---- epilogue: + bias, store ----
    const bool full = (n0 + 128 <= VOCAB);
    #pragma unroll
    for (int mt = 0; mt < 2; mt++) {
        int r0 = m0 + m0w + mt*16 + (lane >> 2);
        #pragma unroll
        for (int nt = 0; nt < 8; nt++) {
            int cn = n0 + n0w + nt*8 + ((lane & 3) << 1);
            float* c0p = C + (size_t)r0 * VOCAB + cn;
            float* c1p = c0p + (size_t)8 * VOCAB;
            if (full) {
                float b0 = __ldg(bias + cn), b1 = __ldg(bias + cn + 1);
                float v0 = acc[mt][nt][0] + b0, v1 = acc[mt][nt][1] + b1;
                float v2 = acc[mt][nt][2] + b0, v3 = acc[mt][nt][3] + b1;
                if (!(((size_t)r0 * VOCAB + cn) & 1)) {
                    *(float2*)c0p = make_float2(v0, v1);
                } else { c0p[0] = v0; c0p[1] = v1; }
                if (!(((size_t)(r0+8) * VOCAB + cn) & 1)) {
                    *(float2*)c1p = make_float2(v2, v3);
                } else { c1p[0] = v2; c1p[1] = v3; }
            } else {
                if (cn < VOCAB) {
                    float b0 = __ldg(bias + cn);
                    c0p[0] = acc[mt][nt][0] + b0;
                    c1p[0] = acc[mt][nt][2] + b0;
                }
                if (cn + 1 < VOCAB) {
                    float b1 = __ldg(bias + cn + 1);
                    c0p[1] = acc[mt][nt][1] + b1;
                    c1p[1] = acc[mt][nt][3] + b1;
                }
            }
        }
    }
}

// ============================================================
extern "C" void kernel_launch(void* const* d_in, const int* in_sizes, int n_in,
                              void* d_out, int out_size)
{
    const float* x    = (const float*)d_in[0];
    const float* Wg   = (const float*)d_in[1];
    const float* bg   = (const float*)d_in[2];
    const float* We   = (const float*)d_in[3];
    const float* be   = (const float*)d_in[4];
    const float* Wo   = (const float*)d_in[5];
    const float* bo   = (const float*)d_in[6];
    const float* Wout = (const float*)d_in[7];
    const float* bout = (const float*)d_in[8];
    float* out = (float*)d_out;

    const int gemm_smem = NSTG * STG_B;     // 110592
    cudaFuncSetAttribute(fused_ctx_kernel, cudaFuncAttributeMaxDynamicSharedMemorySize, CTX_SMEM);
    cudaFuncSetAttribute(gemm_mma_kernel,  cudaFuncAttributeMaxDynamicSharedMemorySize, gemm_smem);

    convert_wout_kernel<<<dim3(16, NT128), 256>>>(Wout);
    fused_ctx_kernel<<<BATCH/CSAMP, 512, CTX_SMEM>>>(x, Wg, bg, We, be, Wo, bo);
    topk_gain_kernel<<<1, 256>>>();
    convert_ctx_kernel<<<(BATCH*HID/2)/256, 256>>>();
    gemm_mma_kernel<<<dim3(MT128, NT128), 256, gemm_smem>>>(bout, out);
}

// round 15
// speedup vs baseline: 1.4136x; 1.0171x over previous
#include <cuda_runtime.h>
#include <cuda_fp16.h>
#include <math.h>
#include <stdint.h>

#define BATCH 2048
#define FEAT  2048
#define HARM  32
#define DIN   (FEAT + 2*HARM)   /* 2112 */
#define NEXP  8
#define EDIM  32
#define HID   1024
#define VOCAB 50257
#define NPAD  50432
#define NT128 394
#define MT128 16

// ---------------- device scratch (no allocations allowed) ----------------
__device__ __align__(16) float  g_ctx0[HID];                 // ctx row 0 (for topk)
__device__ __align__(16) int    g_topidx[20];
__device__ __align__(16) __half g_A_hi[BATCH * HID];         // [2048][1024]
__device__ __align__(16) __half g_B_hi[(size_t)NPAD * HID];  // [NPAD][1024] (Wout^T)

__device__ __forceinline__ uint32_t smem_u32(const void* p) {
    uint32_t a;
    asm("{ .reg .u64 t; cvta.to.shared.u64 t, %1; cvt.u32.u64 %0, t; }" : "=r"(a) : "l"(p));
    return a;
}

#define LDSM_X4(r, a) asm volatile( \
    "ldmatrix.sync.aligned.m8n8.x4.shared.b16 {%0,%1,%2,%3}, [%4];" \
    : "=r"((r)[0]),"=r"((r)[1]),"=r"((r)[2]),"=r"((r)[3]) : "r"(a))
#define MMA16816(c, a, b) asm volatile( \
    "mma.sync.aligned.m16n8k16.row.col.f32.f16.f16.f32 " \
    "{%0,%1,%2,%3},{%4,%5,%6,%7},{%8,%9},{%0,%1,%2,%3};" \
    : "+f"((c)[0]),"+f"((c)[1]),"+f"((c)[2]),"+f"((c)[3]) \
    : "r"((a)[0]),"r"((a)[1]),"r"((a)[2]),"r"((a)[3]), "r"((b)[0]),"r"((b)[1]))
#define CP_ASYNC16(d, s) asm volatile( \
    "cp.async.cg.shared.global [%0], [%1], 16;" :: "r"(d), "l"(s) : "memory")
#define CP_COMMIT() asm volatile("cp.async.commit_group;" ::: "memory")
#define CP_WAIT1()  asm volatile("cp.async.wait_group 1;" ::: "memory")
#define CP_WAIT0()  asm volatile("cp.async.wait_group 0;" ::: "memory")

// ============================================================
// Kernel 1: fused ctx — 8 samples/block, 1024 threads, 4-way split-K.
// Emits fp16 A (ungained) + f32 ctx row 0 only.
// ============================================================
#define CSAMP 8
#define DQ (DIN / 4)             /* 528 */

#define OFF_ENH    0
#define OFF_EO     (CSAMP*DIN*4)                 /* 67584 */
#define OFF_PART   (OFF_EO + CSAMP*256*4)        /* +8192 */
#define OFF_LOGIT  (OFF_PART + 3*CSAMP*256*4)    /* +24576 */
#define OFF_MIXED  (OFF_LOGIT + CSAMP*8*4)
#define OFF_PSUM   (OFF_MIXED + CSAMP*32*4)
#define OFF_GLOG   (OFF_PSUM + 32*4)
#define CTX_SMEM   (OFF_GLOG + 4*64*4)           /* ~102.5 KB */

__global__ __launch_bounds__(1024) void fused_ctx_kernel(
    const float* __restrict__ x,
    const float* __restrict__ Wg, const float* __restrict__ bg,
    const float* __restrict__ We, const float* __restrict__ be,
    const float* __restrict__ Wo, const float* __restrict__ bo)
{
    extern __shared__ __align__(16) char sm[];
    float* enh    = (float*)(sm + OFF_ENH);     // [8][2112]
    float* eo_s   = (float*)(sm + OFF_EO);      // [8][256]
    float* part   = (float*)(sm + OFF_PART);    // [3][8][256]
    float* logits = (float*)(sm + OFF_LOGIT);   // [8][8]
    float* mixed  = (float*)(sm + OFF_MIXED);   // [8][32]
    float* psum   = (float*)(sm + OFF_PSUM);    // [32]
    float* glog   = (float*)(sm + OFF_GLOG);    // [4][8][8]

    const int t = threadIdx.x;
    const int wid = t >> 5, lane = t & 31;
    const int b0 = blockIdx.x * CSAMP;

    // phase 1: 32 warps = (quarter, sample); load quarter-row + partial sum
    {
        int s = wid & 7, q = wid >> 3;
        const float4* xr = (const float4*)(x + (size_t)(b0 + s) * FEAT + q * (FEAT/4));
        float* er = enh + s * DIN + q * (FEAT/4);
        float sum = 0.f;
        #pragma unroll
        for (int i = lane; i < FEAT/16; i += 32) {   // 128 float4 per quarter
            float4 v = xr[i];
            *(float4*)(er + 4*i) = v;
            sum += (v.x + v.y) + (v.z + v.w);
        }
        #pragma unroll
        for (int o = 16; o > 0; o >>= 1) sum += __shfl_xor_sync(0xffffffffu, sum, o);
        if (lane == 0) psum[wid] = sum;
    }
    __syncthreads();
    if (wid < 8) {
        float mean = (psum[wid] + psum[wid+8] + psum[wid+16] + psum[wid+24]) * (1.0f / FEAT);
        float base = 43.98229715025711f * mean;   // 2*pi*7
        float ph = base * (float)(lane + 1);
        float* er = enh + wid * DIN;
        er[FEAT + lane]        = cosf(ph);
        er[FEAT + HARM + lane] = sinf(ph);
    }
    __syncthreads();

    // phase 2a: 256 expert outputs x 4 K-quarters = 1024 threads
    float acc[CSAMP];
    {
        const int kidx = t >> 8;           // 0..3
        const int tt = t & 255;
        const int e = tt >> 5, h = tt & 31;
        const float* wp = We + (size_t)e * DIN * EDIM + h;
        const int d0 = kidx * DQ;
        #pragma unroll
        for (int s = 0; s < CSAMP; s++) acc[s] = 0.f;
        for (int d = d0; d < d0 + DQ; d += 4) {
            float w0 = wp[(size_t)(d+0) * EDIM];
            float w1 = wp[(size_t)(d+1) * EDIM];
            float w2 = wp[(size_t)(d+2) * EDIM];
            float w3 = wp[(size_t)(d+3) * EDIM];
            #pragma unroll
            for (int s = 0; s < CSAMP; s++) {
                float4 ev = *(const float4*)(enh + s*DIN + d);
                float a = acc[s];
                a = fmaf(ev.x, w0, a); a = fmaf(ev.y, w1, a);
                a = fmaf(ev.z, w2, a); a = fmaf(ev.w, w3, a);
                acc[s] = a;
            }
        }
        if (kidx > 0) {
            float* pp = part + (kidx - 1) * CSAMP * 256;
            #pragma unroll
            for (int s = 0; s < CSAMP; s++) pp[s*256 + tt] = acc[s];
        }
    }

    // phase 2b: 8 gates x 4 K-quarters = 32 warps, shuffle-reduced
    {
        const int e = wid & 7, q = wid >> 3;
        const int d0 = q * DQ;
        float ag[CSAMP];
        #pragma unroll
        for (int s = 0; s < CSAMP; s++) ag[s] = 0.f;
        for (int d = d0 + lane; d < d0 + DQ; d += 32) {
            float w = Wg[(size_t)d * NEXP + e];
            #pragma unroll
            for (int s = 0; s < CSAMP; s++)
                ag[s] = fmaf(enh[s*DIN + d], w, ag[s]);
        }
        #pragma unroll
        for (int s = 0; s < CSAMP; s++) {
            float v = ag[s];
            #pragma unroll
            for (int o = 16; o > 0; o >>= 1) v += __shfl_xor_sync(0xffffffffu, v, o);
            if (lane == 0) glog[q*64 + s*8 + e] = v;
        }
    }
    __syncthreads();

    // combine expert partials (kidx=0 acc still in regs of t<256)
    if (t < 256) {
        #pragma unroll
        for (int s = 0; s < CSAMP; s++)
            eo_s[s*256 + t] = acc[s] + part[0*2048 + s*256 + t]
                            + part[1*2048 + s*256 + t] + part[2*2048 + s*256 + t] + be[t];
    }
    if (t < 64) {
        int s = t >> 3, e = t & 7;
        logits[s*8 + e] = glog[s*8 + e] + glog[64 + s*8 + e]
                        + glog[128 + s*8 + e] + glog[192 + s*8 + e] + bg[e];
    }
    __syncthreads();

    // phase 3: softmax per sample
    if (t < CSAMP) {
        float* lg = logits + t*8;
        float mx = lg[0];
        #pragma unroll
        for (int e = 1; e < 8; e++) mx = fmaxf(mx, lg[e]);
        float ss = 0.f;
        #pragma unroll
        for (int e = 0; e < 8; e++) { float ex = expf(lg[e] - mx); lg[e] = ex; ss += ex; }
        float inv = 1.0f / ss;
        #pragma unroll
        for (int e = 0; e < 8; e++) lg[e] *= inv;
    }
    __syncthreads();

    // phase 4: mixed[s][h]
    if (t < 256) {
        int s = t >> 5, h = t & 31;
        float m = 0.f;
        #pragma unroll
        for (int e = 0; e < 8; e++) m = fmaf(logits[s*8 + e], eo_s[s*256 + e*32 + h], m);
        mixed[t] = m;
    }
    __syncthreads();

    // phase 5: ctx -> fp16 A (ungained); f32 row 0 saved for topk
    {
        int o = t;   // 1024 outputs, one per thread
        float a5[CSAMP];
        float bb = bo[o];
        #pragma unroll
        for (int s = 0; s < CSAMP; s++) a5[s] = bb;
        for (int k = 0; k < EDIM; k++) {
            float w = Wo[(size_t)k * HID + o];
            #pragma unroll
            for (int s = 0; s < CSAMP; s++) a5[s] = fmaf(mixed[s*32 + k], w, a5[s]);
        }
        #pragma unroll
        for (int s = 0; s < CSAMP; s++) {
            float c = tanhf(a5[s]);
            g_A_hi[(size_t)(b0 + s) * HID + o] = __float2half_rn(c);
            if (b0 + s == 0) g_ctx0[o] = c;
        }
    }
}

// ============================================================
// Kernel 2: top-20 of ctx[0,:] -> compact index list
// ============================================================
__global__ __launch_bounds__(256) void topk_gain_kernel()
{
    __shared__ float vals[HID];
    __shared__ float rv[256];
    __shared__ int   ri[256];
    const int t = threadIdx.x;
    for (int i = t; i < HID; i += 256) vals[i] = g_ctx0[i];
    __syncthreads();
    for (int it = 0; it < 20; it++) {
        float best = -1e30f; int bi = 0;
        for (int i = t; i < HID; i += 256)
            if (vals[i] > best) { best = vals[i]; bi = i; }
        rv[t] = best; ri[t] = bi;
        __syncthreads();
        for (int s = 128; s > 0; s >>= 1) {
            if (t < s && rv[t + s] > rv[t]) { rv[t] = rv[t + s]; ri[t] = ri[t + s]; }
            __syncthreads();
        }
        if (t == 0) { g_topidx[it] = ri[0]; vals[ri[0]] = -1e30f; }
        __syncthreads();
    }
}

// ============================================================
// Kernel 3: apply gain — double 20 columns of fp16 A (exact: exp+1)
// grid 40 blocks x 1024: block b handles column g_topidx[b>>1],
// rows [ (b&1)*1024, ... ) via 1024 threads.
// ============================================================
__global__ __launch_bounds__(1024) void apply_gain_kernel()
{
    int col = g_topidx[blockIdx.x >> 1];
    int row = (blockIdx.x & 1) * 1024 + threadIdx.x;
    size_t e = (size_t)row * HID + col;
    __half v = g_A_hi[e];
    g_A_hi[e] = __hmul(v, __float2half_rn(2.0f));
}

// ============================================================
// Kernel 4: Wout [K][N] f32 -> g_B_hi [NPAD][K] fp16 (transpose)
// ============================================================
__global__ __launch_bounds__(256) void convert_wout_kernel(const float* __restrict__ W)
{
    __shared__ uint16_t s_hi[128][66];
    const int t = threadIdx.x;
    const int k0 = blockIdx.x * 64;
    const int n0 = blockIdx.y * 128;

    for (int it = 0; it < 32; it++) {
        int idx = it * 256 + t;        // 64k x 128n
        int k = idx >> 7, n = idx & 127;
        int gn = n0 + n;
        float v = (gn < VOCAB) ? __ldg(W + (size_t)(k0 + k) * VOCAB + gn) : 0.f;
        s_hi[n][k] = __half_as_ushort(__float2half_rn(v));
    }
    __syncthreads();

    for (int it = 0; it < 16; it++) {
        int u = it * 256 + t;
        int nn = u >> 5, ku = (u & 31) * 2;
        uint32_t hv = *(uint32_t*)&s_hi[nn][ku];
        size_t e = (size_t)(n0 + nn) * HID + k0 + ku;
        *(uint32_t*)((__half*)g_B_hi + e) = hv;
    }
}

// ============================================================
// Kernel 5: out = A @ B^T + bias via mma.sync fp16
// CTA 128x128, 256 threads, 2 CTAs/SM, BK=64, 3-stage cp.async
// pipeline, one sync/chunk + register double-buffered fragments.
// ============================================================
#define BK 64
#define SROW 72
#define ARR_B (128 * SROW * 2)
#define STG_B (2 * ARR_B)
#define NSTG 3
#define NCHUNK (HID / BK)

__global__ __launch_bounds__(256, 2) void gemm_mma_kernel(
    const float* __restrict__ bias, float* __restrict__ C)
{
    extern __shared__ __align__(16) char sm[];
    const uint32_t sb = smem_u32(sm);
    const int t = threadIdx.x, lane = t & 31, wid = t >> 5;
    const int m0 = blockIdx.x * 128, n0 = blockIdx.y * 128;
    const int m0w = (wid & 3) * 32, n0w = (wid >> 2) * 64;

    float acc[2][8][4];
    #pragma unroll
    for (int i = 0; i < 2; i++)
        #pragma unroll
        for (int j = 0; j < 8; j++)
            #pragma unroll
            for (int q = 0; q < 4; q++) acc[i][j][q] = 0.f;

    const __half* srcA = g_A_hi + (size_t)m0 * HID;
    const __half* srcB = g_B_hi + (size_t)n0 * HID;

    auto issue = [&](int c) {
        uint32_t stg = sb + (uint32_t)(c % NSTG) * STG_B;
        int k0 = c * BK;
        #pragma unroll
        for (int a = 0; a < 2; a++) {
            uint32_t dbase = stg + a * ARR_B;
            const __half* gp = (a == 0 ? srcA : srcB) + k0;
            #pragma unroll
            for (int it = 0; it < 4; it++) {
                int idx = it * 256 + t;
                int row = idx >> 3, seg = idx & 7;
                uint32_t d = dbase + row * (SROW * 2) + seg * 16;
                CP_ASYNC16(d, gp + (size_t)row * HID + seg * 8);
            }
        }
        CP_COMMIT();
    };

    uint32_t ah[2][2][4], bh[2][8][2];
    const int aRowOff = (lane & 15) * (SROW*2);
    const int aColSel = ((lane >> 4) << 3) * 2;
    const int gsel = lane >> 3;
    const int browoff = ((gsel & 1) * 8 + (lane & 7)) * (SROW*2);
    const int bcoloff = ((gsel >> 1) * 8) * 2;

    issue(0); issue(1);
    for (int c = 0; c < NCHUNK; c++) {
        if (c + 1 < NCHUNK) { CP_WAIT1(); } else { CP_WAIT0(); }
        __syncthreads();
        if (c + 2 < NCHUNK) issue(c + 2);

        uint32_t stg = sb + (uint32_t)(c % NSTG) * STG_B;
        uint32_t pAh = stg, pBh = stg + ARR_B;

        {
            uint32_t abase = pAh + aRowOff + aColSel;
            LDSM_X4(ah[0][0], abase + (uint32_t)(m0w) * (SROW*2));
            LDSM_X4(ah[0][1], abase + (uint32_t)(m0w + 16) * (SROW*2));
            uint32_t bbase = pBh + browoff + bcoloff;
            #pragma unroll
            for (int np = 0; np < 4; np++) {
                uint32_t r4[4];
                LDSM_X4(r4, bbase + (uint32_t)(n0w + np*16) * (SROW*2));
                bh[0][2*np  ][0] = r4[0]; bh[0][2*np  ][1] = r4[2];
                bh[0][2*np+1][0] = r4[1]; bh[0][2*np+1][1] = r4[3];
            }
        }

        #pragma unroll
        for (int ks = 0; ks < 4; ks++) {
            const int cur = ks & 1, nxt = cur ^ 1;
            if (ks < 3) {
                int kb2 = (ks + 1) * 16 * 2;
                uint32_t abase = pAh + aRowOff + aColSel + kb2;
                LDSM_X4(ah[nxt][0], abase + (uint32_t)(m0w) * (SROW*2));
                LDSM_X4(ah[nxt][1], abase + (uint32_t)(m0w + 16) * (SROW*2));
                uint32_t bbase = pBh + browoff + bcoloff + kb2;
                #pragma unroll
                for (int np = 0; np < 4; np++) {
                    uint32_t r4[4];
                    LDSM_X4(r4, bbase + (uint32_t)(n0w + np*16) * (SROW*2));
                    bh[nxt][2*np  ][0] = r4[0]; bh[nxt][2*np  ][1] = r4[2];
                    bh[nxt][2*np+1][0] = r4[1]; bh[nxt][2*np+1][1] = r4[3];
                }
            }
            #pragma unroll
            for (int mt = 0; mt < 2; mt++)
                #pragma unroll
                for (int nt = 0; nt < 8; nt++)
                    MMA16816(acc[mt][nt], ah[cur][mt], bh[cur][nt]);
        }
    }

    const bool full = (n0 + 128 <= VOCAB);
    #pragma unroll
    for (int mt = 0; mt < 2; mt++) {
        int r0 = m0 + m0w + mt*16 + (lane >> 2);
        #pragma unroll
        for (int nt = 0; nt < 8; nt++) {
            int cn = n0 + n0w + nt*8 + ((lane & 3) << 1);
            float* c0p = C + (size_t)r0 * VOCAB + cn;
            float* c1p = c0p + (size_t)8 * VOCAB;
            if (full) {
                float b0 = __ldg(bias + cn), b1 = __ldg(bias + cn + 1);
                float v0 = acc[mt][nt][0] + b0, v1 = acc[mt][nt][1] + b1;
                float v2 = acc[mt][nt][2] + b0, v3 = acc[mt][nt][3] + b1;
                if (!(((size_t)r0 * VOCAB + cn) & 1)) {
                    *(float2*)c0p = make_float2(v0, v1);
                } else { c0p[0] = v0; c0p[1] = v1; }
                if (!(((size_t)(r0+8) * VOCAB + cn) & 1)) {
                    *(float2*)c1p = make_float2(v2, v3);
                } else { c1p[0] = v2; c1p[1] = v3; }
            } else {
                if (cn < VOCAB) {
                    float b0 = __ldg(bias + cn);
                    c0p[0] = acc[mt][nt][0] + b0;
                    c1p[0] = acc[mt][nt][2] + b0;
                }
                if (cn + 1 < VOCAB) {
                    float b1 = __ldg(bias + cn + 1);
                    c0p[1] = acc[mt][nt][1] + b1;
                    c1p[1] = acc[mt][nt][3] + b1;
                }
            }
        }
    }
}

// ============================================================
extern "C" void kernel_launch(void* const* d_in, const int* in_sizes, int n_in,
                              void* d_out, int out_size)
{
    const float* x    = (const float*)d_in[0];
    const float* Wg   = (const float*)d_in[1];
    const float* bg   = (const float*)d_in[2];
    const float* We   = (const float*)d_in[3];
    const float* be   = (const float*)d_in[4];
    const float* Wo   = (const float*)d_in[5];
    const float* bo   = (const float*)d_in[6];
    const float* Wout = (const float*)d_in[7];
    const float* bout = (const float*)d_in[8];
    float* out = (float*)d_out;

    const int gemm_smem = NSTG * STG_B;     // 110592
    cudaFuncSetAttribute(fused_ctx_kernel, cudaFuncAttributeMaxDynamicSharedMemorySize, CTX_SMEM);
    cudaFuncSetAttribute(gemm_mma_kernel,  cudaFuncAttributeMaxDynamicSharedMemorySize, gemm_smem);

    convert_wout_kernel<<<dim3(16, NT128), 256>>>(Wout);
    fused_ctx_kernel<<<BATCH/CSAMP, 1024, CTX_SMEM>>>(x, Wg, bg, We, be, Wo, bo);
    topk_gain_kernel<<<1, 256>>>();
    apply_gain_kernel<<<40, 1024>>>();
    gemm_mma_kernel<<<dim3(MT128, NT128), 256, gemm_smem>>>(bout, out);
}

// round 16
// speedup vs baseline: 1.4262x; 1.0089x over previous
#include <cuda_runtime.h>
#include <cuda_fp16.h>
#include <math.h>
#include <stdint.h>

#define BATCH 2048
#define FEAT  2048
#define HARM  32
#define DIN   (FEAT + 2*HARM)   /* 2112 */
#define NEXP  8
#define EDIM  32
#define HID   1024
#define VOCAB 50257
#define NPAD  50432
#define NT128 394
#define MT128 16

// ---------------- device scratch (no allocations allowed) ----------------
__device__ __align__(16) float  g_ctx0[HID];                 // ctx row 0 (for topk)
__device__ __align__(16) int    g_topidx[20];
__device__ __align__(16) __half g_A_hi[BATCH * HID];         // [2048][1024]
__device__ __align__(16) __half g_B_hi[(size_t)NPAD * HID];  // [NPAD][1024] (Wout^T)

// ---------------- side stream for prep overlap (created once, before any
// capture; streams/events are not device-memory allocations) ----------------
static cudaStream_t g_s2;
static cudaEvent_t  g_ev_fork, g_ev_join;
static struct StreamInit {
    StreamInit() {
        cudaStreamCreateWithFlags(&g_s2, cudaStreamNonBlocking);
        cudaEventCreateWithFlags(&g_ev_fork, cudaEventDisableTiming);
        cudaEventCreateWithFlags(&g_ev_join, cudaEventDisableTiming);
    }
} g_stream_init;

__device__ __forceinline__ uint32_t smem_u32(const void* p) {
    uint32_t a;
    asm("{ .reg .u64 t; cvta.to.shared.u64 t, %1; cvt.u32.u64 %0, t; }" : "=r"(a) : "l"(p));
    return a;
}

#define LDSM_X4(r, a) asm volatile( \
    "ldmatrix.sync.aligned.m8n8.x4.shared.b16 {%0,%1,%2,%3}, [%4];" \
    : "=r"((r)[0]),"=r"((r)[1]),"=r"((r)[2]),"=r"((r)[3]) : "r"(a))
#define MMA16816(c, a, b) asm volatile( \
    "mma.sync.aligned.m16n8k16.row.col.f32.f16.f16.f32 " \
    "{%0,%1,%2,%3},{%4,%5,%6,%7},{%8,%9},{%0,%1,%2,%3};" \
    : "+f"((c)[0]),"+f"((c)[1]),"+f"((c)[2]),"+f"((c)[3]) \
    : "r"((a)[0]),"r"((a)[1]),"r"((a)[2]),"r"((a)[3]), "r"((b)[0]),"r"((b)[1]))
#define CP_ASYNC16(d, s) asm volatile( \
    "cp.async.cg.shared.global [%0], [%1], 16;" :: "r"(d), "l"(s) : "memory")
#define CP_COMMIT() asm volatile("cp.async.commit_group;" ::: "memory")
#define CP_WAIT1()  asm volatile("cp.async.wait_group 1;" ::: "memory")
#define CP_WAIT0()  asm volatile("cp.async.wait_group 0;" ::: "memory")

// ============================================================
// Kernel 1: fused ctx — 8 samples/block, 1024 threads, 4-way split-K.
// Emits fp16 A (ungained) + f32 ctx row 0 only.
// ============================================================
#define CSAMP 8
#define DQ (DIN / 4)             /* 528 */

#define OFF_ENH    0
#define OFF_EO     (CSAMP*DIN*4)
#define OFF_PART   (OFF_EO + CSAMP*256*4)
#define OFF_LOGIT  (OFF_PART + 3*CSAMP*256*4)
#define OFF_MIXED  (OFF_LOGIT + CSAMP*8*4)
#define OFF_PSUM   (OFF_MIXED + CSAMP*32*4)
#define OFF_GLOG   (OFF_PSUM + 32*4)
#define CTX_SMEM   (OFF_GLOG + 4*64*4)

__global__ __launch_bounds__(1024) void fused_ctx_kernel(
    const float* __restrict__ x,
    const float* __restrict__ Wg, const float* __restrict__ bg,
    const float* __restrict__ We, const float* __restrict__ be,
    const float* __restrict__ Wo, const float* __restrict__ bo)
{
    extern __shared__ __align__(16) char sm[];
    float* enh    = (float*)(sm + OFF_ENH);
    float* eo_s   = (float*)(sm + OFF_EO);
    float* part   = (float*)(sm + OFF_PART);
    float* logits = (float*)(sm + OFF_LOGIT);
    float* mixed  = (float*)(sm + OFF_MIXED);
    float* psum   = (float*)(sm + OFF_PSUM);
    float* glog   = (float*)(sm + OFF_GLOG);

    const int t = threadIdx.x;
    const int wid = t >> 5, lane = t & 31;
    const int b0 = blockIdx.x * CSAMP;

    {
        int s = wid & 7, q = wid >> 3;
        const float4* xr = (const float4*)(x + (size_t)(b0 + s) * FEAT + q * (FEAT/4));
        float* er = enh + s * DIN + q * (FEAT/4);
        float sum = 0.f;
        #pragma unroll
        for (int i = lane; i < FEAT/16; i += 32) {
            float4 v = xr[i];
            *(float4*)(er + 4*i) = v;
            sum += (v.x + v.y) + (v.z + v.w);
        }
        #pragma unroll
        for (int o = 16; o > 0; o >>= 1) sum += __shfl_xor_sync(0xffffffffu, sum, o);
        if (lane == 0) psum[wid] = sum;
    }
    __syncthreads();
    if (wid < 8) {
        float mean = (psum[wid] + psum[wid+8] + psum[wid+16] + psum[wid+24]) * (1.0f / FEAT);
        float base = 43.98229715025711f * mean;   // 2*pi*7
        float ph = base * (float)(lane + 1);
        float* er = enh + wid * DIN;
        er[FEAT + lane]        = cosf(ph);
        er[FEAT + HARM + lane] = sinf(ph);
    }
    __syncthreads();

    float acc[CSAMP];
    {
        const int kidx = t >> 8;
        const int tt = t & 255;
        const int e = tt >> 5, h = tt & 31;
        const float* wp = We + (size_t)e * DIN * EDIM + h;
        const int d0 = kidx * DQ;
        #pragma unroll
        for (int s = 0; s < CSAMP; s++) acc[s] = 0.f;
        for (int d = d0; d < d0 + DQ; d += 4) {
            float w0 = wp[(size_t)(d+0) * EDIM];
            float w1 = wp[(size_t)(d+1) * EDIM];
            float w2 = wp[(size_t)(d+2) * EDIM];
            float w3 = wp[(size_t)(d+3) * EDIM];
            #pragma unroll
            for (int s = 0; s < CSAMP; s++) {
                float4 ev = *(const float4*)(enh + s*DIN + d);
                float a = acc[s];
                a = fmaf(ev.x, w0, a); a = fmaf(ev.y, w1, a);
                a = fmaf(ev.z, w2, a); a = fmaf(ev.w, w3, a);
                acc[s] = a;
            }
        }
        if (kidx > 0) {
            float* pp = part + (kidx - 1) * CSAMP * 256;
            #pragma unroll
            for (int s = 0; s < CSAMP; s++) pp[s*256 + tt] = acc[s];
        }
    }

    {
        const int e = wid & 7, q = wid >> 3;
        const int d0 = q * DQ;
        float ag[CSAMP];
        #pragma unroll
        for (int s = 0; s < CSAMP; s++) ag[s] = 0.f;
        for (int d = d0 + lane; d < d0 + DQ; d += 32) {
            float w = Wg[(size_t)d * NEXP + e];
            #pragma unroll
            for (int s = 0; s < CSAMP; s++)
                ag[s] = fmaf(enh[s*DIN + d], w, ag[s]);
        }
        #pragma unroll
        for (int s = 0; s < CSAMP; s++) {
            float v = ag[s];
            #pragma unroll
            for (int o = 16; o > 0; o >>= 1) v += __shfl_xor_sync(0xffffffffu, v, o);
            if (lane == 0) glog[q*64 + s*8 + e] = v;
        }
    }
    __syncthreads();

    if (t < 256) {
        #pragma unroll
        for (int s = 0; s < CSAMP; s++)
            eo_s[s*256 + t] = acc[s] + part[0*2048 + s*256 + t]
                            + part[1*2048 + s*256 + t] + part[2*2048 + s*256 + t] + be[t];
    }
    if (t < 64) {
        int s = t >> 3, e = t & 7;
        logits[s*8 + e] = glog[s*8 + e] + glog[64 + s*8 + e]
                        + glog[128 + s*8 + e] + glog[192 + s*8 + e] + bg[e];
    }
    __syncthreads();

    if (t < CSAMP) {
        float* lg = logits + t*8;
        float mx = lg[0];
        #pragma unroll
        for (int e = 1; e < 8; e++) mx = fmaxf(mx, lg[e]);
        float ss = 0.f;
        #pragma unroll
        for (int e = 0; e < 8; e++) { float ex = expf(lg[e] - mx); lg[e] = ex; ss += ex; }
        float inv = 1.0f / ss;
        #pragma unroll
        for (int e = 0; e < 8; e++) lg[e] *= inv;
    }
    __syncthreads();

    if (t < 256) {
        int s = t >> 5, h = t & 31;
        float m = 0.f;
        #pragma unroll
        for (int e = 0; e < 8; e++) m = fmaf(logits[s*8 + e], eo_s[s*256 + e*32 + h], m);
        mixed[t] = m;
    }
    __syncthreads();

    {
        int o = t;
        float a5[CSAMP];
        float bb = bo[o];
        #pragma unroll
        for (int s = 0; s < CSAMP; s++) a5[s] = bb;
        for (int k = 0; k < EDIM; k++) {
            float w = Wo[(size_t)k * HID + o];
            #pragma unroll
            for (int s = 0; s < CSAMP; s++) a5[s] = fmaf(mixed[s*32 + k], w, a5[s]);
        }
        #pragma unroll
        for (int s = 0; s < CSAMP; s++) {
            float c = tanhf(a5[s]);
            g_A_hi[(size_t)(b0 + s) * HID + o] = __float2half_rn(c);
            if (b0 + s == 0) g_ctx0[o] = c;
        }
    }
}

// ============================================================
// Kernel 2: top-20 of ctx[0,:] -> compact index list
// ============================================================
__global__ __launch_bounds__(256) void topk_gain_kernel()
{
    __shared__ float vals[HID];
    __shared__ float rv[256];
    __shared__ int   ri[256];
    const int t = threadIdx.x;
    for (int i = t; i < HID; i += 256) vals[i] = g_ctx0[i];
    __syncthreads();
    for (int it = 0; it < 20; it++) {
        float best = -1e30f; int bi = 0;
        for (int i = t; i < HID; i += 256)
            if (vals[i] > best) { best = vals[i]; bi = i; }
        rv[t] = best; ri[t] = bi;
        __syncthreads();
        for (int s = 128; s > 0; s >>= 1) {
            if (t < s && rv[t + s] > rv[t]) { rv[t] = rv[t + s]; ri[t] = ri[t + s]; }
            __syncthreads();
        }
        if (t == 0) { g_topidx[it] = ri[0]; vals[ri[0]] = -1e30f; }
        __syncthreads();
    }
}

// ============================================================
// Kernel 3: apply gain — double 20 columns of fp16 A (exact: exp+1)
// ============================================================
__global__ __launch_bounds__(1024) void apply_gain_kernel()
{
    int col = g_topidx[blockIdx.x >> 1];
    int row = (blockIdx.x & 1) * 1024 + threadIdx.x;
    size_t e = (size_t)row * HID + col;
    __half v = g_A_hi[e];
    g_A_hi[e] = __hmul(v, __float2half_rn(2.0f));
}

// ============================================================
// Kernel 4: Wout [K][N] f32 -> g_B_hi [NPAD][K] fp16 (transpose)
// (runs on side stream, overlapped with fused_ctx)
// ============================================================
__global__ __launch_bounds__(256) void convert_wout_kernel(const float* __restrict__ W)
{
    __shared__ uint16_t s_hi[128][66];
    const int t = threadIdx.x;
    const int k0 = blockIdx.x * 64;
    const int n0 = blockIdx.y * 128;

    for (int it = 0; it < 32; it++) {
        int idx = it * 256 + t;
        int k = idx >> 7, n = idx & 127;
        int gn = n0 + n;
        float v = (gn < VOCAB) ? __ldg(W + (size_t)(k0 + k) * VOCAB + gn) : 0.f;
        s_hi[n][k] = __half_as_ushort(__float2half_rn(v));
    }
    __syncthreads();

    for (int it = 0; it < 16; it++) {
        int u = it * 256 + t;
        int nn = u >> 5, ku = (u & 31) * 2;
        uint32_t hv = *(uint32_t*)&s_hi[nn][ku];
        size_t e = (size_t)(n0 + nn) * HID + k0 + ku;
        *(uint32_t*)((__half*)g_B_hi + e) = hv;
    }
}

// ============================================================
// Kernel 5: out = A @ B^T + bias via mma.sync fp16
// CTA 128x128, 256 threads, 2 CTAs/SM, BK=64, 3-stage cp.async
// pipeline, one sync/chunk + register double-buffered fragments.
// ============================================================
#define BK 64
#define SROW 72
#define ARR_B (128 * SROW * 2)
#define STG_B (2 * ARR_B)
#define NSTG 3
#define NCHUNK (HID / BK)

__global__ __launch_bounds__(256, 2) void gemm_mma_kernel(
    const float* __restrict__ bias, float* __restrict__ C)
{
    extern __shared__ __align__(16) char sm[];
    const uint32_t sb = smem_u32(sm);
    const int t = threadIdx.x, lane = t & 31, wid = t >> 5;
    const int m0 = blockIdx.x * 128, n0 = blockIdx.y * 128;
    const int m0w = (wid & 3) * 32, n0w = (wid >> 2) * 64;

    float acc[2][8][4];
    #pragma unroll
    for (int i = 0; i < 2; i++)
        #pragma unroll
        for (int j = 0; j < 8; j++)
            #pragma unroll
            for (int q = 0; q < 4; q++) acc[i][j][q] = 0.f;

    const __half* srcA = g_A_hi + (size_t)m0 * HID;
    const __half* srcB = g_B_hi + (size_t)n0 * HID;

    auto issue = [&](int c) {
        uint32_t stg = sb + (uint32_t)(c % NSTG) * STG_B;
        int k0 = c * BK;
        #pragma unroll
        for (int a = 0; a < 2; a++) {
            uint32_t dbase = stg + a * ARR_B;
            const __half* gp = (a == 0 ? srcA : srcB) + k0;
            #pragma unroll
            for (int it = 0; it < 4; it++) {
                int idx = it * 256 + t;
                int row = idx >> 3, seg = idx & 7;
                uint32_t d = dbase + row * (SROW * 2) + seg * 16;
                CP_ASYNC16(d, gp + (size_t)row * HID + seg * 8);
            }
        }
        CP_COMMIT();
    };

    uint32_t ah[2][2][4], bh[2][8][2];
    const int aRowOff = (lane & 15) * (SROW*2);
    const int aColSel = ((lane >> 4) << 3) * 2;
    const int gsel = lane >> 3;
    const int browoff = ((gsel & 1) * 8 + (lane & 7)) * (SROW*2);
    const int bcoloff = ((gsel >> 1) * 8) * 2;

    issue(0); issue(1);
    for (int c = 0; c < NCHUNK; c++) {
        if (c + 1 < NCHUNK) { CP_WAIT1(); } else { CP_WAIT0(); }
        __syncthreads();
        if (c + 2 < NCHUNK) issue(c + 2);

        uint32_t stg = sb + (uint32_t)(c % NSTG) * STG_B;
        uint32_t pAh = stg, pBh = stg + ARR_B;

        {
            uint32_t abase = pAh + aRowOff + aColSel;
            LDSM_X4(ah[0][0], abase + (uint32_t)(m0w) * (SROW*2));
            LDSM_X4(ah[0][1], abase + (uint32_t)(m0w + 16) * (SROW*2));
            uint32_t bbase = pBh + browoff + bcoloff;
            #pragma unroll
            for (int np = 0; np < 4; np++) {
                uint32_t r4[4];
                LDSM_X4(r4, bbase + (uint32_t)(n0w + np*16) * (SROW*2));
                bh[0][2*np  ][0] = r4[0]; bh[0][2*np  ][1] = r4[2];
                bh[0][2*np+1][0] = r4[1]; bh[0][2*np+1][1] = r4[3];
            }
        }

        #pragma unroll
        for (int ks = 0; ks < 4; ks++) {
            const int cur = ks & 1, nxt = cur ^ 1;
            if (ks < 3) {
                int kb2 = (ks + 1) * 16 * 2;
                uint32_t abase = pAh + aRowOff + aColSel + kb2;
                LDSM_X4(ah[nxt][0], abase + (uint32_t)(m0w) * (SROW*2));
                LDSM_X4(ah[nxt][1], abase + (uint32_t)(m0w + 16) * (SROW*2));
                uint32_t bbase = pBh + browoff + bcoloff + kb2;
                #pragma unroll
                for (int np = 0; np < 4; np++) {
                    uint32_t r4[4];
                    LDSM_X4(r4, bbase + (uint32_t)(n0w + np*16) * (SROW*2));
                    bh[nxt][2*np  ][0] = r4[0]; bh[nxt][2*np  ][1] = r4[2];
                    bh[nxt][2*np+1][0] = r4[1]; bh[nxt][2*np+1][1] = r4[3];
                }
            }
            #pragma unroll
            for (int mt = 0; mt < 2; mt++)
                #pragma unroll
                for (int nt = 0; nt < 8; nt++)
                    MMA16816(acc[mt][nt], ah[cur][mt], bh[cur][nt]);
        }
    }

    const bool full = (n0 + 128 <= VOCAB);
    #pragma unroll
    for (int mt = 0; mt < 2; mt++) {
        int r0 = m0 + m0w + mt*16 + (lane >> 2);
        #pragma unroll
        for (int nt = 0; nt < 8; nt++) {
            int cn = n0 + n0w + nt*8 + ((lane & 3) << 1);
            float* c0p = C + (size_t)r0 * VOCAB + cn;
            float* c1p = c0p + (size_t)8 * VOCAB;
            if (full) {
                float b0 = __ldg(bias + cn), b1 = __ldg(bias + cn + 1);
                float v0 = acc[mt][nt][0] + b0, v1 = acc[mt][nt][1] + b1;
                float v2 = acc[mt][nt][2] + b0, v3 = acc[mt][nt][3] + b1;
                if (!(((size_t)r0 * VOCAB + cn) & 1)) {
                    *(float2*)c0p = make_float2(v0, v1);
                } else { c0p[0] = v0; c0p[1] = v1; }
                if (!(((size_t)(r0+8) * VOCAB + cn) & 1)) {
                    *(float2*)c1p = make_float2(v2, v3);
                } else { c1p[0] = v2; c1p[1] = v3; }
            } else {
                if (cn < VOCAB) {
                    float b0 = __ldg(bias + cn);
                    c0p[0] = acc[mt][nt][0] + b0;
                    c1p[0] = acc[mt][nt][2] + b0;
                }
                if (cn + 1 < VOCAB) {
                    float b1 = __ldg(bias + cn + 1);
                    c0p[1] = acc[mt][nt][1] + b1;
                    c1p[1] = acc[mt][nt][3] + b1;
                }
            }
        }
    }
}

// ============================================================
extern "C" void kernel_launch(void* const* d_in, const int* in_sizes, int n_in,
                              void* d_out, int out_size)
{
    const float* x    = (const float*)d_in[0];
    const float* Wg   = (const float*)d_in[1];
    const float* bg   = (const float*)d_in[2];
    const float* We   = (const float*)d_in[3];
    const float* be   = (const float*)d_in[4];
    const float* Wo   = (const float*)d_in[5];
    const float* bo   = (const float*)d_in[6];
    const float* Wout = (const float*)d_in[7];
    const float* bout = (const float*)d_in[8];
    float* out = (float*)d_out;

    const int gemm_smem = NSTG * STG_B;     // 110592
    cudaFuncSetAttribute(fused_ctx_kernel, cudaFuncAttributeMaxDynamicSharedMemorySize, CTX_SMEM);
    cudaFuncSetAttribute(gemm_mma_kernel,  cudaFuncAttributeMaxDynamicSharedMemorySize, gemm_smem);

    // fork: convert_wout on side stream, overlapped with the ctx chain
    cudaEventRecord(g_ev_fork, 0);
    cudaStreamWaitEvent(g_s2, g_ev_fork, 0);
    convert_wout_kernel<<<dim3(16, NT128), 256, 0, g_s2>>>(Wout);
    cudaEventRecord(g_ev_join, g_s2);

    // main chain (null stream)
    fused_ctx_kernel<<<BATCH/CSAMP, 1024, CTX_SMEM>>>(x, Wg, bg, We, be, Wo, bo);
    topk_gain_kernel<<<1, 256>>>();
    apply_gain_kernel<<<40, 1024>>>();

    // join before GEMM (needs g_B_hi)
    cudaStreamWaitEvent(0, g_ev_join, 0);
    gemm_mma_kernel<<<dim3(MT128, NT128), 256, gemm_smem>>>(bout, out);
}